// round 1
// baseline (speedup 1.0000x reference)
#include <cuda_runtime.h>

#define BATCH  4
#define SEQ    1024
#define DMODEL 1024
#define NHEAD  16
#define DEPTH  64
#define MROWS  (BATCH * SEQ)

// Scratch (allocation-free rule: device globals)
__device__ float g_Q[(size_t)MROWS * DMODEL];
__device__ float g_K[(size_t)MROWS * DMODEL];
__device__ float g_V[(size_t)MROWS * DMODEL];
__device__ float g_O[(size_t)MROWS * DMODEL];

// ---------------------------------------------------------------------------
// GEMM: C[M,N] = (A[M,K] @ W[N,K]^T + bias[N]) * scale
// Tile 64x64x16, 256 threads, 4x4 per thread. Smem stride 68 (16B-aligned
// float4 rows, bank-spread).
// ---------------------------------------------------------------------------
#define GBK  16
#define GSTR 68

__global__ __launch_bounds__(256)
void gemm_nt_bias(const float* __restrict__ A, const float* __restrict__ W,
                  const float* __restrict__ bias, float* __restrict__ C,
                  int M, int N, int K, float scale)
{
    __shared__ float As[GBK][GSTR];
    __shared__ float Ws[GBK][GSTR];

    const int t  = threadIdx.x;
    const int tx = t & 15;
    const int ty = t >> 4;
    const int bm = blockIdx.y * 64;
    const int bn = blockIdx.x * 64;
    const int lrow = t >> 2;         // 0..63
    const int lk   = (t & 3) * 4;    // 0,4,8,12

    float acc[4][4] = {};

    for (int k0 = 0; k0 < K; k0 += GBK) {
        float4 av = *(const float4*)(A + (size_t)(bm + lrow) * K + (k0 + lk));
        float4 wv = *(const float4*)(W + (size_t)(bn + lrow) * K + (k0 + lk));
        As[lk + 0][lrow] = av.x; As[lk + 1][lrow] = av.y;
        As[lk + 2][lrow] = av.z; As[lk + 3][lrow] = av.w;
        Ws[lk + 0][lrow] = wv.x; Ws[lk + 1][lrow] = wv.y;
        Ws[lk + 2][lrow] = wv.z; Ws[lk + 3][lrow] = wv.w;
        __syncthreads();

        #pragma unroll
        for (int kk = 0; kk < GBK; kk++) {
            float4 a4 = *(const float4*)&As[kk][ty * 4];
            float4 b4 = *(const float4*)&Ws[kk][tx * 4];
            float ar[4] = {a4.x, a4.y, a4.z, a4.w};
            float br[4] = {b4.x, b4.y, b4.z, b4.w};
            #pragma unroll
            for (int m = 0; m < 4; m++)
                #pragma unroll
                for (int n = 0; n < 4; n++)
                    acc[m][n] = fmaf(ar[m], br[n], acc[m][n]);
        }
        __syncthreads();
    }

    #pragma unroll
    for (int m = 0; m < 4; m++) {
        const size_t row = (size_t)(bm + ty * 4 + m);
        #pragma unroll
        for (int n = 0; n < 4; n++) {
            const int col = bn + tx * 4 + n;
            C[row * N + col] = (acc[m][n] + bias[col]) * scale;
        }
    }
}

// ---------------------------------------------------------------------------
// Flash attention: one block = one (b,h) pair x one 64-row q tile.
// Q already carries the 1/sqrt(depth) scale. mask applied as + mask*(-1e9).
// Smem: Qt,Kt transposed [d][row] (stride 68), Vs row-major [k][d], Ps [q][k].
// ---------------------------------------------------------------------------
#define AST 68

__global__ __launch_bounds__(256)
void attn_flash(const float* __restrict__ mask)
{
    extern __shared__ float sm[];
    float* Qt = sm;                  // 64 x AST
    float* Kt = sm + 64 * AST;       // 64 x AST
    float* Vs = sm + 2 * 64 * AST;   // 64 x AST
    float* Ps = sm + 3 * 64 * AST;   // 64 x AST

    const int t  = threadIdx.x;
    const int tx = t & 15;
    const int ty = t >> 4;
    const int q0 = blockIdx.x * 64;
    const int bh = blockIdx.y;
    const int b  = bh >> 4;
    const int h  = bh & 15;

    const float* Qg = g_Q + (size_t)b * SEQ * DMODEL + h * DEPTH;
    const float* Kg = g_K + (size_t)b * SEQ * DMODEL + h * DEPTH;
    const float* Vg = g_V + (size_t)b * SEQ * DMODEL + h * DEPTH;

    // Load Q tile (64 rows x 64 depth), transpose into Qt[d][row]
    #pragma unroll
    for (int i = 0; i < 4; i++) {
        int e = i * 1024 + t * 4;
        int row = e >> 6, d = e & 63;
        float4 v = *(const float4*)(Qg + (size_t)(q0 + row) * DMODEL + d);
        Qt[(d + 0) * AST + row] = v.x; Qt[(d + 1) * AST + row] = v.y;
        Qt[(d + 2) * AST + row] = v.z; Qt[(d + 3) * AST + row] = v.w;
    }

    float Oa[4][4] = {};
    float rmax[4], rsum[4];
    #pragma unroll
    for (int m = 0; m < 4; m++) { rmax[m] = -1e30f; rsum[m] = 0.f; }

    for (int k0 = 0; k0 < SEQ; k0 += 64) {
        __syncthreads();  // prior iter done reading Kt/Vs/Ps (also fences Q tile)
        #pragma unroll
        for (int i = 0; i < 4; i++) {
            int e = i * 1024 + t * 4;
            int row = e >> 6, d = e & 63;
            float4 kv = *(const float4*)(Kg + (size_t)(k0 + row) * DMODEL + d);
            Kt[(d + 0) * AST + row] = kv.x; Kt[(d + 1) * AST + row] = kv.y;
            Kt[(d + 2) * AST + row] = kv.z; Kt[(d + 3) * AST + row] = kv.w;
            float4 vv = *(const float4*)(Vg + (size_t)(k0 + row) * DMODEL + d);
            *(float4*)&Vs[row * AST + d] = vv;
        }
        __syncthreads();

        // S = Q @ K^T  (4x4 per thread)
        float s[4][4] = {};
        #pragma unroll 16
        for (int d = 0; d < 64; d++) {
            float4 q4 = *(const float4*)&Qt[d * AST + ty * 4];
            float4 k4 = *(const float4*)&Kt[d * AST + tx * 4];
            float qr[4] = {q4.x, q4.y, q4.z, q4.w};
            float kr[4] = {k4.x, k4.y, k4.z, k4.w};
            #pragma unroll
            for (int m = 0; m < 4; m++)
                #pragma unroll
                for (int n = 0; n < 4; n++)
                    s[m][n] = fmaf(qr[m], kr[n], s[m][n]);
        }

        // mask * (-1e9)
        #pragma unroll
        for (int m = 0; m < 4; m++) {
            float4 mv = *(const float4*)(mask + (size_t)(q0 + ty * 4 + m) * SEQ
                                               + k0 + tx * 4);
            s[m][0] -= 1e9f * mv.x; s[m][1] -= 1e9f * mv.y;
            s[m][2] -= 1e9f * mv.z; s[m][3] -= 1e9f * mv.w;
        }

        // Online softmax (row stats reduced across the 16 tx lanes)
        #pragma unroll
        for (int m = 0; m < 4; m++) {
            float tm = fmaxf(fmaxf(s[m][0], s[m][1]), fmaxf(s[m][2], s[m][3]));
            #pragma unroll
            for (int o = 8; o > 0; o >>= 1)
                tm = fmaxf(tm, __shfl_xor_sync(0xffffffffu, tm, o));
            float nm   = fmaxf(rmax[m], tm);
            float corr = __expf(rmax[m] - nm);
            rmax[m] = nm;
            float ps = 0.f;
            #pragma unroll
            for (int n = 0; n < 4; n++) {
                s[m][n] = __expf(s[m][n] - nm);
                ps += s[m][n];
            }
            #pragma unroll
            for (int o = 8; o > 0; o >>= 1)
                ps += __shfl_xor_sync(0xffffffffu, ps, o);
            rsum[m] = rsum[m] * corr + ps;
            #pragma unroll
            for (int n = 0; n < 4; n++) Oa[m][n] *= corr;
            *(float4*)&Ps[(ty * 4 + m) * AST + tx * 4] =
                make_float4(s[m][0], s[m][1], s[m][2], s[m][3]);
        }
        __syncthreads();

        // O += P @ V
        #pragma unroll 8
        for (int k = 0; k < 64; k++) {
            float4 v4 = *(const float4*)&Vs[k * AST + tx * 4];
            float vr[4] = {v4.x, v4.y, v4.z, v4.w};
            float pr[4];
            #pragma unroll
            for (int m = 0; m < 4; m++) pr[m] = Ps[(ty * 4 + m) * AST + k];
            #pragma unroll
            for (int m = 0; m < 4; m++)
                #pragma unroll
                for (int n = 0; n < 4; n++)
                    Oa[m][n] = fmaf(pr[m], vr[n], Oa[m][n]);
        }
    }

    // Normalize and write back into [b, s, h*64 + d] layout (merged heads)
    float* Og = g_O + (size_t)b * SEQ * DMODEL + h * DEPTH;
    #pragma unroll
    for (int m = 0; m < 4; m++) {
        float inv = 1.0f / rsum[m];
        *(float4*)(Og + (size_t)(q0 + ty * 4 + m) * DMODEL + tx * 4) =
            make_float4(Oa[m][0] * inv, Oa[m][1] * inv,
                        Oa[m][2] * inv, Oa[m][3] * inv);
    }
}

// ---------------------------------------------------------------------------
extern "C" void kernel_launch(void* const* d_in, const int* in_sizes, int n_in,
                              void* d_out, int out_size)
{
    (void)in_sizes; (void)n_in; (void)out_size;
    const float* q    = (const float*)d_in[0];
    const float* k    = (const float*)d_in[1];
    const float* v    = (const float*)d_in[2];
    const float* mask = (const float*)d_in[3];
    const float* wq_w = (const float*)d_in[4];
    const float* wq_b = (const float*)d_in[5];
    const float* wk_w = (const float*)d_in[6];
    const float* wk_b = (const float*)d_in[7];
    const float* wv_w = (const float*)d_in[8];
    const float* wv_b = (const float*)d_in[9];
    const float* pl_w = (const float*)d_in[10];
    const float* pl_b = (const float*)d_in[11];
    float* out = (float*)d_out;

    float *Qp, *Kp, *Vp, *Op;
    cudaGetSymbolAddress((void**)&Qp, g_Q);
    cudaGetSymbolAddress((void**)&Kp, g_K);
    cudaGetSymbolAddress((void**)&Vp, g_V);
    cudaGetSymbolAddress((void**)&Op, g_O);

    dim3 blk(256);
    dim3 gg(DMODEL / 64, MROWS / 64);

    // Projections (1/sqrt(depth)=0.125 folded into Q)
    gemm_nt_bias<<<gg, blk>>>(q, wq_w, wq_b, Qp, MROWS, DMODEL, DMODEL, 0.125f);
    gemm_nt_bias<<<gg, blk>>>(k, wk_w, wk_b, Kp, MROWS, DMODEL, DMODEL, 1.0f);
    gemm_nt_bias<<<gg, blk>>>(v, wv_w, wv_b, Vp, MROWS, DMODEL, DMODEL, 1.0f);

    // Attention
    size_t smem = (size_t)4 * 64 * AST * sizeof(float);  // 69,632 B
    cudaFuncSetAttribute(attn_flash, cudaFuncAttributeMaxDynamicSharedMemorySize,
                         (int)smem);
    attn_flash<<<dim3(SEQ / 64, BATCH * NHEAD), blk, smem>>>(mask);

    // Output projection
    gemm_nt_bias<<<gg, blk>>>(Op, pl_w, pl_b, out, MROWS, DMODEL, DMODEL, 1.0f);
}

// round 5
// speedup vs baseline: 1.6810x; 1.6810x over previous
#include <cuda_runtime.h>
#include <cuda_fp16.h>
#include <cstdint>

#define BATCH  4
#define SEQ    1024
#define DM     1024
#define NHEAD  16
#define DEPTH  64
#define MROWS  (BATCH * SEQ)

// ---------------- scratch (device globals; allocation-free rule) ------------
__device__ float g_Q[(size_t)MROWS * DM];
__device__ float g_K[(size_t)MROWS * DM];
__device__ float g_V[(size_t)MROWS * DM];
__device__ float g_O[(size_t)MROWS * DM];
__device__ __half g_xhi[(size_t)MROWS * DM];
__device__ __half g_xlo[(size_t)MROWS * DM];
__device__ __half g_whi[(size_t)DM * DM];
__device__ __half g_wlo[(size_t)DM * DM];

// ---------------- small helpers ---------------------------------------------
__device__ __forceinline__ uint32_t smem_u32(const void* p) {
    uint32_t a;
    asm("{ .reg .u64 t; cvta.to.shared.u64 t, %1; cvt.u32.u64 %0, t; }"
        : "=r"(a) : "l"(p));
    return a;
}
__device__ __forceinline__ void ldm_x4(uint32_t* r, uint32_t addr) {
    asm volatile("ldmatrix.sync.aligned.m8n8.x4.shared.b16 {%0,%1,%2,%3}, [%4];"
                 : "=r"(r[0]), "=r"(r[1]), "=r"(r[2]), "=r"(r[3]) : "r"(addr));
}
__device__ __forceinline__ void mma16816(float* d, const uint32_t* a,
                                         const uint32_t* b) {
    asm volatile(
        "mma.sync.aligned.m16n8k16.row.col.f32.f16.f16.f32 "
        "{%0,%1,%2,%3}, {%4,%5,%6,%7}, {%8,%9}, {%0,%1,%2,%3};"
        : "+f"(d[0]), "+f"(d[1]), "+f"(d[2]), "+f"(d[3])
        : "r"(a[0]), "r"(a[1]), "r"(a[2]), "r"(a[3]), "r"(b[0]), "r"(b[1]));
}

// ---------------- fp32 -> fp16 hi/lo split ----------------------------------
__global__ __launch_bounds__(256)
void split_f16(const float* __restrict__ x, __half* __restrict__ hi,
               __half* __restrict__ lo, int n)
{
    int i = (blockIdx.x * 256 + threadIdx.x) * 4;
    if (i >= n) return;
    float4 v = *(const float4*)(x + i);
    float a[4] = {v.x, v.y, v.z, v.w};
    __half h2[4], l2[4];
    #pragma unroll
    for (int j = 0; j < 4; j++) {
        __half h = __float2half_rn(a[j]);
        h2[j] = h;
        l2[j] = __float2half_rn(a[j] - __half2float(h));
    }
    *(uint2*)(hi + i) = *(uint2*)h2;
    *(uint2*)(lo + i) = *(uint2*)l2;
}

// ---------------- HMMA GEMM: C = (A @ W^T + bias) * scale -------------------
// A[M,1024], W[N,1024] given as fp16 (hi,lo). 3-pass split product, fp32 acc.
// CTA 128x128, K-chunk 64. 8 warps: warp_m = wid&3 (32 rows), warp_n = wid>>2
// (64 cols). smem rows padded to 72 halves (144B) -> conflict-free ldmatrix.
#define BM 128
#define BN 128
#define BK 64
#define SKP 72                       // padded row stride in halves
#define TILE_H (BM * SKP)            // halves per smem tile (9216)
#define GEMM_SMEM (4 * TILE_H * 2)   // 73728 bytes

__global__ __launch_bounds__(256)
void gemm_hmma(const __half* __restrict__ Ahi, const __half* __restrict__ Alo,
               const __half* __restrict__ Whi, const __half* __restrict__ Wlo,
               const float* __restrict__ bias, float* __restrict__ C,
               float scale)
{
    extern __shared__ __half sh[];
    __half* sAh = sh;
    __half* sAl = sh + TILE_H;
    __half* sWh = sh + 2 * TILE_H;
    __half* sWl = sh + 3 * TILE_H;
    const uint32_t bAh = smem_u32(sAh);
    const uint32_t bAl = smem_u32(sAl);
    const uint32_t bWh = smem_u32(sWh);
    const uint32_t bWl = smem_u32(sWl);

    const int t      = threadIdx.x;
    const int lane   = t & 31;
    const int wid    = t >> 5;
    const int warp_m = wid & 3;
    const int warp_n = wid >> 2;
    const int sub    = lane >> 3;
    const int l7     = lane & 7;
    const int bm     = blockIdx.y * BM;
    const int bn     = blockIdx.x * BN;

    float acc[2][8][4];
    #pragma unroll
    for (int i = 0; i < 2; i++)
        #pragma unroll
        for (int j = 0; j < 8; j++)
            #pragma unroll
            for (int c = 0; c < 4; c++) acc[i][j][c] = 0.f;

    // precomputed fragment smem byte offsets (k16=0)
    const uint32_t a_off =
        ((warp_m * 32 + (l7 | ((sub & 1) << 3))) * SKP + ((sub >> 1) << 3)) * 2;
    const uint32_t b_off =
        ((warp_n * 64 + (l7 + ((sub >> 1) << 3))) * SKP + ((sub & 1) << 3)) * 2;

    for (int k0 = 0; k0 < DM; k0 += BK) {
        __syncthreads();
        #pragma unroll
        for (int j = 0; j < 4; j++) {
            int lin = t + j * 256;            // 0..1023
            int row = lin >> 3;
            int c8  = lin & 7;
            size_t ga = (size_t)(bm + row) * DM + k0 + c8 * 8;
            size_t gw = (size_t)(bn + row) * DM + k0 + c8 * 8;
            int so = row * SKP + c8 * 8;
            *(uint4*)(sAh + so) = *(const uint4*)(Ahi + ga);
            *(uint4*)(sAl + so) = *(const uint4*)(Alo + ga);
            *(uint4*)(sWh + so) = *(const uint4*)(Whi + gw);
            *(uint4*)(sWl + so) = *(const uint4*)(Wlo + gw);
        }
        __syncthreads();

        #pragma unroll
        for (int k16 = 0; k16 < 4; k16++) {
            const uint32_t ko = k16 * 32;     // 16 halves = 32 bytes
            uint32_t ah[2][4], al[2][4], bh[8][2], bl[8][2];
            #pragma unroll
            for (int im = 0; im < 2; im++) {
                uint32_t off = a_off + im * (16 * SKP * 2) + ko;
                ldm_x4(ah[im], bAh + off);
                ldm_x4(al[im], bAl + off);
            }
            #pragma unroll
            for (int jn16 = 0; jn16 < 4; jn16++) {
                uint32_t off = b_off + jn16 * (16 * SKP * 2) + ko;
                uint32_t r[4];
                ldm_x4(r, bWh + off);
                bh[jn16 * 2][0] = r[0]; bh[jn16 * 2][1] = r[1];
                bh[jn16 * 2 + 1][0] = r[2]; bh[jn16 * 2 + 1][1] = r[3];
                ldm_x4(r, bWl + off);
                bl[jn16 * 2][0] = r[0]; bl[jn16 * 2][1] = r[1];
                bl[jn16 * 2 + 1][0] = r[2]; bl[jn16 * 2 + 1][1] = r[3];
            }
            #pragma unroll
            for (int im = 0; im < 2; im++)
                #pragma unroll
                for (int jn = 0; jn < 8; jn++) {
                    mma16816(acc[im][jn], ah[im], bh[jn]);
                    mma16816(acc[im][jn], ah[im], bl[jn]);
                    mma16816(acc[im][jn], al[im], bh[jn]);
                }
        }
    }

    // epilogue
    const int g  = lane >> 2;
    const int tc = (lane & 3) * 2;
    #pragma unroll
    for (int im = 0; im < 2; im++) {
        const int r0 = bm + warp_m * 32 + im * 16 + g;
        #pragma unroll
        for (int jn = 0; jn < 8; jn++) {
            const int c = bn + warp_n * 64 + jn * 8 + tc;
            const float b0 = bias[c], b1 = bias[c + 1];
            *(float2*)(C + (size_t)r0 * DM + c) =
                make_float2((acc[im][jn][0] + b0) * scale,
                            (acc[im][jn][1] + b1) * scale);
            *(float2*)(C + (size_t)(r0 + 8) * DM + c) =
                make_float2((acc[im][jn][2] + b0) * scale,
                            (acc[im][jn][3] + b1) * scale);
        }
    }
}

// ---------------- fp32 flash attention (unchanged from R1) ------------------
#define AST 68

__global__ __launch_bounds__(256)
void attn_flash(const float* __restrict__ mask)
{
    extern __shared__ float smf[];
    float* Qt = smf;
    float* Kt = smf + 64 * AST;
    float* Vs = smf + 2 * 64 * AST;
    float* Ps = smf + 3 * 64 * AST;

    const int t  = threadIdx.x;
    const int tx = t & 15;
    const int ty = t >> 4;
    const int q0 = blockIdx.x * 64;
    const int bh = blockIdx.y;
    const int b  = bh >> 4;
    const int h  = bh & 15;

    const float* Qg = g_Q + (size_t)b * SEQ * DM + h * DEPTH;
    const float* Kg = g_K + (size_t)b * SEQ * DM + h * DEPTH;
    const float* Vg = g_V + (size_t)b * SEQ * DM + h * DEPTH;

    #pragma unroll
    for (int i = 0; i < 4; i++) {
        int e = i * 1024 + t * 4;
        int row = e >> 6, d = e & 63;
        float4 v = *(const float4*)(Qg + (size_t)(q0 + row) * DM + d);
        Qt[(d + 0) * AST + row] = v.x; Qt[(d + 1) * AST + row] = v.y;
        Qt[(d + 2) * AST + row] = v.z; Qt[(d + 3) * AST + row] = v.w;
    }

    float Oa[4][4] = {};
    float rmax[4], rsum[4];
    #pragma unroll
    for (int m = 0; m < 4; m++) { rmax[m] = -1e30f; rsum[m] = 0.f; }

    for (int k0 = 0; k0 < SEQ; k0 += 64) {
        __syncthreads();
        #pragma unroll
        for (int i = 0; i < 4; i++) {
            int e = i * 1024 + t * 4;
            int row = e >> 6, d = e & 63;
            float4 kv = *(const float4*)(Kg + (size_t)(k0 + row) * DM + d);
            Kt[(d + 0) * AST + row] = kv.x; Kt[(d + 1) * AST + row] = kv.y;
            Kt[(d + 2) * AST + row] = kv.z; Kt[(d + 3) * AST + row] = kv.w;
            float4 vv = *(const float4*)(Vg + (size_t)(k0 + row) * DM + d);
            *(float4*)&Vs[row * AST + d] = vv;
        }
        __syncthreads();

        float s[4][4] = {};
        #pragma unroll 16
        for (int d = 0; d < 64; d++) {
            float4 q4 = *(const float4*)&Qt[d * AST + ty * 4];
            float4 k4 = *(const float4*)&Kt[d * AST + tx * 4];
            float qr[4] = {q4.x, q4.y, q4.z, q4.w};
            float kr[4] = {k4.x, k4.y, k4.z, k4.w};
            #pragma unroll
            for (int m = 0; m < 4; m++)
                #pragma unroll
                for (int n = 0; n < 4; n++)
                    s[m][n] = fmaf(qr[m], kr[n], s[m][n]);
        }

        #pragma unroll
        for (int m = 0; m < 4; m++) {
            float4 mv = *(const float4*)(mask + (size_t)(q0 + ty * 4 + m) * SEQ
                                               + k0 + tx * 4);
            s[m][0] -= 1e9f * mv.x; s[m][1] -= 1e9f * mv.y;
            s[m][2] -= 1e9f * mv.z; s[m][3] -= 1e9f * mv.w;
        }

        #pragma unroll
        for (int m = 0; m < 4; m++) {
            float tm = fmaxf(fmaxf(s[m][0], s[m][1]), fmaxf(s[m][2], s[m][3]));
            #pragma unroll
            for (int o = 8; o > 0; o >>= 1)
                tm = fmaxf(tm, __shfl_xor_sync(0xffffffffu, tm, o));
            float nm   = fmaxf(rmax[m], tm);
            float corr = __expf(rmax[m] - nm);
            rmax[m] = nm;
            float ps = 0.f;
            #pragma unroll
            for (int n = 0; n < 4; n++) {
                s[m][n] = __expf(s[m][n] - nm);
                ps += s[m][n];
            }
            #pragma unroll
            for (int o = 8; o > 0; o >>= 1)
                ps += __shfl_xor_sync(0xffffffffu, ps, o);
            rsum[m] = rsum[m] * corr + ps;
            #pragma unroll
            for (int n = 0; n < 4; n++) Oa[m][n] *= corr;
            *(float4*)&Ps[(ty * 4 + m) * AST + tx * 4] =
                make_float4(s[m][0], s[m][1], s[m][2], s[m][3]);
        }
        __syncthreads();

        #pragma unroll 8
        for (int k = 0; k < 64; k++) {
            float4 v4 = *(const float4*)&Vs[k * AST + tx * 4];
            float vr[4] = {v4.x, v4.y, v4.z, v4.w};
            float pr[4];
            #pragma unroll
            for (int m = 0; m < 4; m++) pr[m] = Ps[(ty * 4 + m) * AST + k];
            #pragma unroll
            for (int m = 0; m < 4; m++)
                #pragma unroll
                for (int n = 0; n < 4; n++)
                    Oa[m][n] = fmaf(pr[m], vr[n], Oa[m][n]);
        }
    }

    float* Og = g_O + (size_t)b * SEQ * DM + h * DEPTH;
    #pragma unroll
    for (int m = 0; m < 4; m++) {
        float inv = 1.0f / rsum[m];
        *(float4*)(Og + (size_t)(q0 + ty * 4 + m) * DM + tx * 4) =
            make_float4(Oa[m][0] * inv, Oa[m][1] * inv,
                        Oa[m][2] * inv, Oa[m][3] * inv);
    }
}

// ---------------------------------------------------------------------------
extern "C" void kernel_launch(void* const* d_in, const int* in_sizes, int n_in,
                              void* d_out, int out_size)
{
    (void)in_sizes; (void)n_in; (void)out_size;
    const float* q    = (const float*)d_in[0];
    const float* k    = (const float*)d_in[1];
    const float* v    = (const float*)d_in[2];
    const float* mask = (const float*)d_in[3];
    const float* wq_w = (const float*)d_in[4];
    const float* wq_b = (const float*)d_in[5];
    const float* wk_w = (const float*)d_in[6];
    const float* wk_b = (const float*)d_in[7];
    const float* wv_w = (const float*)d_in[8];
    const float* wv_b = (const float*)d_in[9];
    const float* pl_w = (const float*)d_in[10];
    const float* pl_b = (const float*)d_in[11];
    float* out = (float*)d_out;

    float *Qp, *Kp, *Vp, *Op;
    __half *xhi, *xlo, *whi, *wlo;
    cudaGetSymbolAddress((void**)&Qp, g_Q);
    cudaGetSymbolAddress((void**)&Kp, g_K);
    cudaGetSymbolAddress((void**)&Vp, g_V);
    cudaGetSymbolAddress((void**)&Op, g_O);
    cudaGetSymbolAddress((void**)&xhi, g_xhi);
    cudaGetSymbolAddress((void**)&xlo, g_xlo);
    cudaGetSymbolAddress((void**)&whi, g_whi);
    cudaGetSymbolAddress((void**)&wlo, g_wlo);

    cudaFuncSetAttribute(gemm_hmma, cudaFuncAttributeMaxDynamicSharedMemorySize,
                         GEMM_SMEM);
    size_t asmem = (size_t)4 * 64 * AST * sizeof(float);
    cudaFuncSetAttribute(attn_flash, cudaFuncAttributeMaxDynamicSharedMemorySize,
                         (int)asmem);

    const int NX = MROWS * DM;   // 4M
    const int NW = DM * DM;      // 1M
    dim3 gg(DM / BN, MROWS / BM);   // (8, 32)

    // Q projection (scale 1/sqrt(64) folded in)
    split_f16<<<NX / 1024, 256>>>(q, xhi, xlo, NX);
    split_f16<<<NW / 1024, 256>>>(wq_w, whi, wlo, NW);
    gemm_hmma<<<gg, 256, GEMM_SMEM>>>(xhi, xlo, whi, wlo, wq_b, Qp, 0.125f);
    // K projection
    split_f16<<<NX / 1024, 256>>>(k, xhi, xlo, NX);
    split_f16<<<NW / 1024, 256>>>(wk_w, whi, wlo, NW);
    gemm_hmma<<<gg, 256, GEMM_SMEM>>>(xhi, xlo, whi, wlo, wk_b, Kp, 1.0f);
    // V projection
    split_f16<<<NX / 1024, 256>>>(v, xhi, xlo, NX);
    split_f16<<<NW / 1024, 256>>>(wv_w, whi, wlo, NW);
    gemm_hmma<<<gg, 256, GEMM_SMEM>>>(xhi, xlo, whi, wlo, wv_b, Vp, 1.0f);

    // attention (fp32)
    attn_flash<<<dim3(SEQ / 64, BATCH * NHEAD), 256, asmem>>>(mask);

    // output projection
    split_f16<<<NX / 1024, 256>>>(Op, xhi, xlo, NX);
    split_f16<<<NW / 1024, 256>>>(pl_w, whi, wlo, NW);
    gemm_hmma<<<gg, 256, GEMM_SMEM>>>(xhi, xlo, whi, wlo, pl_b, out, 1.0f);
}

// round 6
// speedup vs baseline: 2.3396x; 1.3918x over previous
#include <cuda_runtime.h>
#include <cuda_fp16.h>
#include <cstdint>

#define BATCH  4
#define SEQ    1024
#define DM     1024
#define NHEAD  16
#define DEPTH  64
#define MROWS  (BATCH * SEQ)

// ---------------- scratch (device globals; allocation-free rule) ------------
__device__ __half g_Qh[(size_t)MROWS * DM];
__device__ __half g_Ql[(size_t)MROWS * DM];
__device__ __half g_Kh[(size_t)MROWS * DM];
__device__ __half g_Kl[(size_t)MROWS * DM];
__device__ __half g_Vh[(size_t)MROWS * DM];
__device__ __half g_Vl[(size_t)MROWS * DM];
__device__ __half g_Oh[(size_t)MROWS * DM];
__device__ __half g_Ol[(size_t)MROWS * DM];
__device__ __half g_xhi[(size_t)MROWS * DM];
__device__ __half g_xlo[(size_t)MROWS * DM];
__device__ __half g_whi[(size_t)DM * DM];
__device__ __half g_wlo[(size_t)DM * DM];

// ---------------- small helpers ---------------------------------------------
__device__ __forceinline__ uint32_t smem_u32(const void* p) {
    uint32_t a;
    asm("{ .reg .u64 t; cvta.to.shared.u64 t, %1; cvt.u32.u64 %0, t; }"
        : "=r"(a) : "l"(p));
    return a;
}
__device__ __forceinline__ void ldm_x4(uint32_t* r, uint32_t addr) {
    asm volatile("ldmatrix.sync.aligned.m8n8.x4.shared.b16 {%0,%1,%2,%3}, [%4];"
                 : "=r"(r[0]), "=r"(r[1]), "=r"(r[2]), "=r"(r[3]) : "r"(addr));
}
__device__ __forceinline__ void ldm_x4_t(uint32_t* r, uint32_t addr) {
    asm volatile("ldmatrix.sync.aligned.m8n8.x4.trans.shared.b16 {%0,%1,%2,%3}, [%4];"
                 : "=r"(r[0]), "=r"(r[1]), "=r"(r[2]), "=r"(r[3]) : "r"(addr));
}
__device__ __forceinline__ void mma16816(float* d, const uint32_t* a,
                                         const uint32_t* b) {
    asm volatile(
        "mma.sync.aligned.m16n8k16.row.col.f32.f16.f16.f32 "
        "{%0,%1,%2,%3}, {%4,%5,%6,%7}, {%8,%9}, {%0,%1,%2,%3};"
        : "+f"(d[0]), "+f"(d[1]), "+f"(d[2]), "+f"(d[3])
        : "r"(a[0]), "r"(a[1]), "r"(a[2]), "r"(a[3]), "r"(b[0]), "r"(b[1]));
}
// pack (a,b) into hi/lo half2 words (low half = a)
__device__ __forceinline__ void split2(float a, float b, uint32_t& hi,
                                       uint32_t& lo) {
    __half ha = __float2half_rn(a), hb = __float2half_rn(b);
    __half la = __float2half_rn(a - __half2float(ha));
    __half lb = __float2half_rn(b - __half2float(hb));
    hi = (uint32_t)__half_as_ushort(ha) | ((uint32_t)__half_as_ushort(hb) << 16);
    lo = (uint32_t)__half_as_ushort(la) | ((uint32_t)__half_as_ushort(lb) << 16);
}

// ---------------- fp32 -> fp16 hi/lo split (inputs & weights only) ----------
__global__ __launch_bounds__(256)
void split_f16(const float* __restrict__ x, __half* __restrict__ hi,
               __half* __restrict__ lo, int n)
{
    int i = (blockIdx.x * 256 + threadIdx.x) * 4;
    if (i >= n) return;
    float4 v = *(const float4*)(x + i);
    float a[4] = {v.x, v.y, v.z, v.w};
    __half h2[4], l2[4];
    #pragma unroll
    for (int j = 0; j < 4; j++) {
        __half h = __float2half_rn(a[j]);
        h2[j] = h;
        l2[j] = __float2half_rn(a[j] - __half2float(h));
    }
    *(uint2*)(hi + i) = *(uint2*)h2;
    *(uint2*)(lo + i) = *(uint2*)l2;
}

// ---------------- HMMA GEMM: C = (A @ W^T + bias) * scale -------------------
// 3-pass hi/lo split product, fp32 acc. Epilogue writes either fp32 (Cf) or
// fp16 hi/lo pair (Chi/Clo) for downstream MMA consumers.
#define BM 128
#define BN 128
#define BK 64
#define SKP 72
#define TILE_H (BM * SKP)
#define GEMM_SMEM (4 * TILE_H * 2)   // 73728 bytes

__global__ __launch_bounds__(256)
void gemm_hmma(const __half* __restrict__ Ahi, const __half* __restrict__ Alo,
               const __half* __restrict__ Whi, const __half* __restrict__ Wlo,
               const float* __restrict__ bias,
               float* __restrict__ Cf, __half* __restrict__ Chi,
               __half* __restrict__ Clo, float scale)
{
    extern __shared__ __half sh[];
    __half* sAh = sh;
    __half* sAl = sh + TILE_H;
    __half* sWh = sh + 2 * TILE_H;
    __half* sWl = sh + 3 * TILE_H;
    const uint32_t bAh = smem_u32(sAh);
    const uint32_t bAl = smem_u32(sAl);
    const uint32_t bWh = smem_u32(sWh);
    const uint32_t bWl = smem_u32(sWl);

    const int t      = threadIdx.x;
    const int lane   = t & 31;
    const int wid    = t >> 5;
    const int warp_m = wid & 3;
    const int warp_n = wid >> 2;
    const int sub    = lane >> 3;
    const int l7     = lane & 7;
    const int bm     = blockIdx.y * BM;
    const int bn     = blockIdx.x * BN;

    float acc[2][8][4];
    #pragma unroll
    for (int i = 0; i < 2; i++)
        #pragma unroll
        for (int j = 0; j < 8; j++)
            #pragma unroll
            for (int c = 0; c < 4; c++) acc[i][j][c] = 0.f;

    const uint32_t a_off =
        ((warp_m * 32 + (l7 | ((sub & 1) << 3))) * SKP + ((sub >> 1) << 3)) * 2;
    const uint32_t b_off =
        ((warp_n * 64 + (l7 + ((sub >> 1) << 3))) * SKP + ((sub & 1) << 3)) * 2;

    for (int k0 = 0; k0 < DM; k0 += BK) {
        __syncthreads();
        #pragma unroll
        for (int j = 0; j < 4; j++) {
            int lin = t + j * 256;
            int row = lin >> 3;
            int c8  = lin & 7;
            size_t ga = (size_t)(bm + row) * DM + k0 + c8 * 8;
            size_t gw = (size_t)(bn + row) * DM + k0 + c8 * 8;
            int so = row * SKP + c8 * 8;
            *(uint4*)(sAh + so) = *(const uint4*)(Ahi + ga);
            *(uint4*)(sAl + so) = *(const uint4*)(Alo + ga);
            *(uint4*)(sWh + so) = *(const uint4*)(Whi + gw);
            *(uint4*)(sWl + so) = *(const uint4*)(Wlo + gw);
        }
        __syncthreads();

        #pragma unroll
        for (int k16 = 0; k16 < 4; k16++) {
            const uint32_t ko = k16 * 32;
            uint32_t ah[2][4], al[2][4], bh[8][2], bl[8][2];
            #pragma unroll
            for (int im = 0; im < 2; im++) {
                uint32_t off = a_off + im * (16 * SKP * 2) + ko;
                ldm_x4(ah[im], bAh + off);
                ldm_x4(al[im], bAl + off);
            }
            #pragma unroll
            for (int jn16 = 0; jn16 < 4; jn16++) {
                uint32_t off = b_off + jn16 * (16 * SKP * 2) + ko;
                uint32_t r[4];
                ldm_x4(r, bWh + off);
                bh[jn16 * 2][0] = r[0]; bh[jn16 * 2][1] = r[1];
                bh[jn16 * 2 + 1][0] = r[2]; bh[jn16 * 2 + 1][1] = r[3];
                ldm_x4(r, bWl + off);
                bl[jn16 * 2][0] = r[0]; bl[jn16 * 2][1] = r[1];
                bl[jn16 * 2 + 1][0] = r[2]; bl[jn16 * 2 + 1][1] = r[3];
            }
            #pragma unroll
            for (int im = 0; im < 2; im++)
                #pragma unroll
                for (int jn = 0; jn < 8; jn++) {
                    mma16816(acc[im][jn], ah[im], bh[jn]);
                    mma16816(acc[im][jn], ah[im], bl[jn]);
                    mma16816(acc[im][jn], al[im], bh[jn]);
                }
        }
    }

    const int g  = lane >> 2;
    const int tc = (lane & 3) * 2;
    #pragma unroll
    for (int im = 0; im < 2; im++) {
        const int r0 = bm + warp_m * 32 + im * 16 + g;
        #pragma unroll
        for (int jn = 0; jn < 8; jn++) {
            const int c = bn + warp_n * 64 + jn * 8 + tc;
            const float b0 = bias[c], b1 = bias[c + 1];
            float v0 = (acc[im][jn][0] + b0) * scale;
            float v1 = (acc[im][jn][1] + b1) * scale;
            float v2 = (acc[im][jn][2] + b0) * scale;
            float v3 = (acc[im][jn][3] + b1) * scale;
            if (Cf) {
                *(float2*)(Cf + (size_t)r0 * DM + c) = make_float2(v0, v1);
                *(float2*)(Cf + (size_t)(r0 + 8) * DM + c) = make_float2(v2, v3);
            } else {
                uint32_t hi, lo;
                split2(v0, v1, hi, lo);
                *(uint32_t*)(Chi + (size_t)r0 * DM + c) = hi;
                *(uint32_t*)(Clo + (size_t)r0 * DM + c) = lo;
                split2(v2, v3, hi, lo);
                *(uint32_t*)(Chi + (size_t)(r0 + 8) * DM + c) = hi;
                *(uint32_t*)(Clo + (size_t)(r0 + 8) * DM + c) = lo;
            }
        }
    }
}

// ---------------- HMMA flash attention --------------------------------------
// Block = 128 q rows x one (b,h). 8 warps, warp = 16 q rows x full key width.
// S = QK^T 3-pass split; softmax warp-local; PV 3-pass with in-register
// P fragments and ldmatrix.trans V fragments. Writes O as fp16 hi/lo.
#define ATK  128                      // keys per chunk
#define ASKP 72
#define ATILE (128 * ASKP)
#define ATTN_SMEM (4 * ATILE * 2)     // 73728 bytes

__global__ __launch_bounds__(256)
void attn_mma(const float* __restrict__ mask)
{
    extern __shared__ __half sh[];
    __half* sKh = sh;
    __half* sKl = sh + ATILE;
    __half* sVh = sh + 2 * ATILE;
    __half* sVl = sh + 3 * ATILE;
    const uint32_t bKh = smem_u32(sKh);
    const uint32_t bKl = smem_u32(sKl);
    const uint32_t bVh = smem_u32(sVh);
    const uint32_t bVl = smem_u32(sVl);

    const int t    = threadIdx.x;
    const int lane = t & 31;
    const int wid  = t >> 5;
    const int sub  = lane >> 3;
    const int l7   = lane & 7;
    const int g    = lane >> 2;
    const int c2   = (lane & 3) * 2;

    const int q0 = blockIdx.x * 128;
    const int bh = blockIdx.y;
    const int b  = bh >> 4;
    const int h  = bh & 15;

    const size_t base = (size_t)b * SEQ * DM + h * DEPTH;
    const __half* Qhb = g_Qh + base;
    const __half* Qlb = g_Ql + base;
    const __half* Khb = g_Kh + base;
    const __half* Klb = g_Kl + base;
    const __half* Vhb = g_Vh + base;
    const __half* Vlb = g_Vl + base;

    // ---- stage Q tile, load fragments to registers ----
    #pragma unroll
    for (int j = 0; j < 4; j++) {
        int lin = t + j * 256;
        int row = lin >> 3;
        int c8  = (lin & 7) * 8;
        size_t go = (size_t)(q0 + row) * DM + c8;
        int so = row * ASKP + c8;
        *(uint4*)(sKh + so) = *(const uint4*)(Qhb + go);
        *(uint4*)(sKl + so) = *(const uint4*)(Qlb + go);
    }
    __syncthreads();
    uint32_t qh[4][4], ql[4][4];
    #pragma unroll
    for (int kk = 0; kk < 4; kk++) {
        uint32_t off = ((wid * 16 + (l7 | ((sub & 1) << 3))) * ASKP
                        + ((sub >> 1) << 3) + kk * 16) * 2;
        ldm_x4(qh[kk], bKh + off);
        ldm_x4(ql[kk], bKl + off);
    }

    float oacc[8][4];
    #pragma unroll
    for (int j = 0; j < 8; j++)
        #pragma unroll
        for (int c = 0; c < 4; c++) oacc[j][c] = 0.f;
    float rmax[2] = {-1e30f, -1e30f};
    float rsum[2] = {0.f, 0.f};

    const int mrow = q0 + wid * 16 + g;

    for (int k0 = 0; k0 < SEQ; k0 += ATK) {
        __syncthreads();   // prior iter done reading smem (or Q frags done)
        #pragma unroll
        for (int j = 0; j < 4; j++) {
            int lin = t + j * 256;
            int row = lin >> 3;
            int c8  = (lin & 7) * 8;
            size_t go = (size_t)(k0 + row) * DM + c8;
            int so = row * ASKP + c8;
            *(uint4*)(sKh + so) = *(const uint4*)(Khb + go);
            *(uint4*)(sKl + so) = *(const uint4*)(Klb + go);
            *(uint4*)(sVh + so) = *(const uint4*)(Vhb + go);
            *(uint4*)(sVl + so) = *(const uint4*)(Vlb + go);
        }
        __syncthreads();

        // ---- S = Q @ K^T ----
        float sacc[16][4];
        #pragma unroll
        for (int j = 0; j < 16; j++)
            #pragma unroll
            for (int c = 0; c < 4; c++) sacc[j][c] = 0.f;

        #pragma unroll
        for (int kk = 0; kk < 4; kk++) {
            #pragma unroll
            for (int jp = 0; jp < 8; jp++) {
                uint32_t rh[4], rl[4];
                uint32_t off = ((jp * 16 + l7 + ((sub >> 1) << 3)) * ASKP
                                + ((sub & 1) << 3) + kk * 16) * 2;
                ldm_x4(rh, bKh + off);
                ldm_x4(rl, bKl + off);
                mma16816(sacc[2 * jp],     qh[kk], rh);
                mma16816(sacc[2 * jp],     qh[kk], rl);
                mma16816(sacc[2 * jp],     ql[kk], rh);
                mma16816(sacc[2 * jp + 1], qh[kk], rh + 2);
                mma16816(sacc[2 * jp + 1], qh[kk], rl + 2);
                mma16816(sacc[2 * jp + 1], ql[kk], rh + 2);
            }
        }

        // ---- mask ----
        #pragma unroll
        for (int j = 0; j < 16; j++) {
            int col = k0 + j * 8 + c2;
            float2 m0 = *(const float2*)(mask + (size_t)mrow * SEQ + col);
            float2 m1 = *(const float2*)(mask + (size_t)(mrow + 8) * SEQ + col);
            sacc[j][0] -= 1e9f * m0.x; sacc[j][1] -= 1e9f * m0.y;
            sacc[j][2] -= 1e9f * m1.x; sacc[j][3] -= 1e9f * m1.y;
        }

        // ---- online softmax (rows g, g+8; stats across 4-lane row group) ----
        #pragma unroll
        for (int r = 0; r < 2; r++) {
            float mx = -1e30f;
            #pragma unroll
            for (int j = 0; j < 16; j++)
                mx = fmaxf(mx, fmaxf(sacc[j][2 * r], sacc[j][2 * r + 1]));
            mx = fmaxf(mx, __shfl_xor_sync(0xffffffffu, mx, 1));
            mx = fmaxf(mx, __shfl_xor_sync(0xffffffffu, mx, 2));
            float nm   = fmaxf(rmax[r], mx);
            float corr = __expf(rmax[r] - nm);
            rmax[r] = nm;
            float ps = 0.f;
            #pragma unroll
            for (int j = 0; j < 16; j++) {
                float p0 = __expf(sacc[j][2 * r] - nm);
                float p1 = __expf(sacc[j][2 * r + 1] - nm);
                sacc[j][2 * r] = p0; sacc[j][2 * r + 1] = p1;
                ps += p0 + p1;
            }
            ps += __shfl_xor_sync(0xffffffffu, ps, 1);
            ps += __shfl_xor_sync(0xffffffffu, ps, 2);
            rsum[r] = rsum[r] * corr + ps;
            #pragma unroll
            for (int jn = 0; jn < 8; jn++) {
                oacc[jn][2 * r]     *= corr;
                oacc[jn][2 * r + 1] *= corr;
            }
        }

        // ---- O += P @ V ----
        #pragma unroll
        for (int kk = 0; kk < 8; kk++) {
            uint32_t ph[4], pl[4];
            split2(sacc[2 * kk][0],     sacc[2 * kk][1],     ph[0], pl[0]);
            split2(sacc[2 * kk][2],     sacc[2 * kk][3],     ph[1], pl[1]);
            split2(sacc[2 * kk + 1][0], sacc[2 * kk + 1][1], ph[2], pl[2]);
            split2(sacc[2 * kk + 1][2], sacc[2 * kk + 1][3], ph[3], pl[3]);
            #pragma unroll
            for (int jd = 0; jd < 4; jd++) {
                uint32_t vh4[4], vl4[4];
                uint32_t off = ((kk * 16 + ((sub & 1) << 3) + l7) * ASKP
                                + jd * 16 + ((sub >> 1) << 3)) * 2;
                ldm_x4_t(vh4, bVh + off);
                ldm_x4_t(vl4, bVl + off);
                mma16816(oacc[2 * jd],     ph, vh4);
                mma16816(oacc[2 * jd],     ph, vl4);
                mma16816(oacc[2 * jd],     pl, vh4);
                mma16816(oacc[2 * jd + 1], ph, vh4 + 2);
                mma16816(oacc[2 * jd + 1], ph, vl4 + 2);
                mma16816(oacc[2 * jd + 1], pl, vh4 + 2);
            }
        }
    }

    // ---- epilogue: normalize, write fp16 hi/lo ----
    const float inv0 = 1.0f / rsum[0];
    const float inv1 = 1.0f / rsum[1];
    const int orow = q0 + wid * 16 + g;
    __half* Ohb = g_Oh + base + (size_t)orow * DM;
    __half* Olb = g_Ol + base + (size_t)orow * DM;
    #pragma unroll
    for (int jn = 0; jn < 8; jn++) {
        int cc = jn * 8 + c2;
        uint32_t hi, lo;
        split2(oacc[jn][0] * inv0, oacc[jn][1] * inv0, hi, lo);
        *(uint32_t*)(Ohb + cc) = hi;
        *(uint32_t*)(Olb + cc) = lo;
        split2(oacc[jn][2] * inv1, oacc[jn][3] * inv1, hi, lo);
        *(uint32_t*)(Ohb + 8 * DM + cc) = hi;
        *(uint32_t*)(Olb + 8 * DM + cc) = lo;
    }
}

// ---------------------------------------------------------------------------
extern "C" void kernel_launch(void* const* d_in, const int* in_sizes, int n_in,
                              void* d_out, int out_size)
{
    (void)in_sizes; (void)n_in; (void)out_size;
    const float* q    = (const float*)d_in[0];
    const float* k    = (const float*)d_in[1];
    const float* v    = (const float*)d_in[2];
    const float* mask = (const float*)d_in[3];
    const float* wq_w = (const float*)d_in[4];
    const float* wq_b = (const float*)d_in[5];
    const float* wk_w = (const float*)d_in[6];
    const float* wk_b = (const float*)d_in[7];
    const float* wv_w = (const float*)d_in[8];
    const float* wv_b = (const float*)d_in[9];
    const float* pl_w = (const float*)d_in[10];
    const float* pl_b = (const float*)d_in[11];
    float* out = (float*)d_out;

    __half *Qh, *Ql, *Kh, *Kl, *Vh, *Vl, *Oh, *Ol, *xhi, *xlo, *whi, *wlo;
    cudaGetSymbolAddress((void**)&Qh, g_Qh);
    cudaGetSymbolAddress((void**)&Ql, g_Ql);
    cudaGetSymbolAddress((void**)&Kh, g_Kh);
    cudaGetSymbolAddress((void**)&Kl, g_Kl);
    cudaGetSymbolAddress((void**)&Vh, g_Vh);
    cudaGetSymbolAddress((void**)&Vl, g_Vl);
    cudaGetSymbolAddress((void**)&Oh, g_Oh);
    cudaGetSymbolAddress((void**)&Ol, g_Ol);
    cudaGetSymbolAddress((void**)&xhi, g_xhi);
    cudaGetSymbolAddress((void**)&xlo, g_xlo);
    cudaGetSymbolAddress((void**)&whi, g_whi);
    cudaGetSymbolAddress((void**)&wlo, g_wlo);

    cudaFuncSetAttribute(gemm_hmma, cudaFuncAttributeMaxDynamicSharedMemorySize,
                         GEMM_SMEM);
    cudaFuncSetAttribute(attn_mma, cudaFuncAttributeMaxDynamicSharedMemorySize,
                         ATTN_SMEM);

    const int NX = MROWS * DM;
    const int NW = DM * DM;
    dim3 gg(DM / BN, MROWS / BM);   // (8, 32)

    // Q projection (1/sqrt(64) folded in), epilogue writes fp16 hi/lo
    split_f16<<<NX / 1024, 256>>>(q, xhi, xlo, NX);
    split_f16<<<NW / 1024, 256>>>(wq_w, whi, wlo, NW);
    gemm_hmma<<<gg, 256, GEMM_SMEM>>>(xhi, xlo, whi, wlo, wq_b,
                                      nullptr, Qh, Ql, 0.125f);
    split_f16<<<NX / 1024, 256>>>(k, xhi, xlo, NX);
    split_f16<<<NW / 1024, 256>>>(wk_w, whi, wlo, NW);
    gemm_hmma<<<gg, 256, GEMM_SMEM>>>(xhi, xlo, whi, wlo, wk_b,
                                      nullptr, Kh, Kl, 1.0f);
    split_f16<<<NX / 1024, 256>>>(v, xhi, xlo, NX);
    split_f16<<<NW / 1024, 256>>>(wv_w, whi, wlo, NW);
    gemm_hmma<<<gg, 256, GEMM_SMEM>>>(xhi, xlo, whi, wlo, wv_b,
                                      nullptr, Vh, Vl, 1.0f);

    // HMMA flash attention (writes fp16 hi/lo O)
    attn_mma<<<dim3(SEQ / 128, BATCH * NHEAD), 256, ATTN_SMEM>>>(mask);

    // output projection (fp32 out)
    split_f16<<<NW / 1024, 256>>>(pl_w, whi, wlo, NW);
    gemm_hmma<<<gg, 256, GEMM_SMEM>>>(Oh, Ol, whi, wlo, pl_b,
                                      out, nullptr, nullptr, 1.0f);
}

// round 7
// speedup vs baseline: 2.5266x; 1.0799x over previous
#include <cuda_runtime.h>
#include <cuda_fp16.h>
#include <cstdint>

#define BATCH  4
#define SEQ    1024
#define DM     1024
#define NHEAD  16
#define DEPTH  64
#define MROWS  (BATCH * SEQ)

// ---------------- scratch (device globals; allocation-free rule) ------------
__device__ __half g_Qh[(size_t)MROWS * DM];
__device__ __half g_Ql[(size_t)MROWS * DM];
__device__ __half g_Kh[(size_t)MROWS * DM];
__device__ __half g_Kl[(size_t)MROWS * DM];
__device__ __half g_Vh[(size_t)MROWS * DM];
__device__ __half g_Vl[(size_t)MROWS * DM];
__device__ __half g_Oh[(size_t)MROWS * DM];
__device__ __half g_Ol[(size_t)MROWS * DM];
__device__ __half g_xhi[(size_t)MROWS * DM];
__device__ __half g_xlo[(size_t)MROWS * DM];
__device__ __half g_whi[(size_t)DM * DM];
__device__ __half g_wlo[(size_t)DM * DM];

// ---------------- helpers ----------------------------------------------------
__device__ __forceinline__ uint32_t smem_u32(const void* p) {
    uint32_t a;
    asm("{ .reg .u64 t; cvta.to.shared.u64 t, %1; cvt.u32.u64 %0, t; }"
        : "=r"(a) : "l"(p));
    return a;
}
__device__ __forceinline__ void ldm_x4(uint32_t* r, uint32_t addr) {
    asm volatile("ldmatrix.sync.aligned.m8n8.x4.shared.b16 {%0,%1,%2,%3}, [%4];"
                 : "=r"(r[0]), "=r"(r[1]), "=r"(r[2]), "=r"(r[3]) : "r"(addr));
}
__device__ __forceinline__ void ldm_x4_t(uint32_t* r, uint32_t addr) {
    asm volatile("ldmatrix.sync.aligned.m8n8.x4.trans.shared.b16 {%0,%1,%2,%3}, [%4];"
                 : "=r"(r[0]), "=r"(r[1]), "=r"(r[2]), "=r"(r[3]) : "r"(addr));
}
__device__ __forceinline__ void mma16816(float* d, const uint32_t* a,
                                         const uint32_t* b) {
    asm volatile(
        "mma.sync.aligned.m16n8k16.row.col.f32.f16.f16.f32 "
        "{%0,%1,%2,%3}, {%4,%5,%6,%7}, {%8,%9}, {%0,%1,%2,%3};"
        : "+f"(d[0]), "+f"(d[1]), "+f"(d[2]), "+f"(d[3])
        : "r"(a[0]), "r"(a[1]), "r"(a[2]), "r"(a[3]), "r"(b[0]), "r"(b[1]));
}
__device__ __forceinline__ void split2(float a, float b, uint32_t& hi,
                                       uint32_t& lo) {
    __half ha = __float2half_rn(a), hb = __float2half_rn(b);
    __half la = __float2half_rn(a - __half2float(ha));
    __half lb = __float2half_rn(b - __half2float(hb));
    hi = (uint32_t)__half_as_ushort(ha) | ((uint32_t)__half_as_ushort(hb) << 16);
    lo = (uint32_t)__half_as_ushort(la) | ((uint32_t)__half_as_ushort(lb) << 16);
}
#define CP_ASYNC16(saddr, gptr) \
    asm volatile("cp.async.cg.shared.global [%0], [%1], 16;" \
                 :: "r"(saddr), "l"(gptr))
#define CP_COMMIT() asm volatile("cp.async.commit_group;")
#define CP_WAIT1()  asm volatile("cp.async.wait_group 1;")
#define CP_WAIT0()  asm volatile("cp.async.wait_group 0;")

// ---------------- fp32 -> fp16 hi/lo split -----------------------------------
__global__ __launch_bounds__(256)
void split_f16(const float* __restrict__ x, __half* __restrict__ hi,
               __half* __restrict__ lo, int n)
{
    int i = (blockIdx.x * 256 + threadIdx.x) * 4;
    if (i >= n) return;
    float4 v = *(const float4*)(x + i);
    float a[4] = {v.x, v.y, v.z, v.w};
    __half h2[4], l2[4];
    #pragma unroll
    for (int j = 0; j < 4; j++) {
        __half h = __float2half_rn(a[j]);
        h2[j] = h;
        l2[j] = __float2half_rn(a[j] - __half2float(h));
    }
    *(uint2*)(hi + i) = *(uint2*)h2;
    *(uint2*)(lo + i) = *(uint2*)l2;
}

// ---------------- HMMA GEMM with cp.async 2-stage pipeline ------------------
// C = (A @ W^T + bias) * scale.  BK=32, padded stride 40 halves.
#define BM 128
#define BN 128
#define BKG 32
#define SKPG 40
#define GT_H (128 * SKPG)            // halves per tile (5120)
#define GSTAGE_H (4 * GT_H)          // halves per stage (20480)
#define GEMM_SMEM (2 * GSTAGE_H * 2) // 81920 bytes

__device__ __forceinline__ void gemm_issue(uint32_t sb, int buf, int k0,
    const __half* A0, const __half* A1, const __half* W0, const __half* W1,
    int t)
{
    const __half* bases[4] = {A0, A1, W0, W1};
    const uint32_t stb = sb + buf * (GSTAGE_H * 2);
    #pragma unroll
    for (int j = 0; j < 8; j++) {
        const int tile = j >> 1;
        const int r = t + (j & 1) * 256;   // 0..511
        const int row = r >> 2, c16 = r & 3;
        const __half* gp = bases[tile] + (size_t)row * DM + k0 + c16 * 8;
        uint32_t sa = stb + (tile * GT_H + row * SKPG + c16 * 8) * 2;
        CP_ASYNC16(sa, gp);
    }
    CP_COMMIT();
}

__global__ void __launch_bounds__(256, 2)
gemm_hmma(const __half* __restrict__ Ahi, const __half* __restrict__ Alo,
          const __half* __restrict__ Whi, const __half* __restrict__ Wlo,
          const float* __restrict__ bias,
          float* __restrict__ Cf, __half* __restrict__ Chi,
          __half* __restrict__ Clo, float scale)
{
    extern __shared__ __half sh[];
    const uint32_t sb = smem_u32(sh);

    const int t      = threadIdx.x;
    const int lane   = t & 31;
    const int wid    = t >> 5;
    const int warp_m = wid & 3;
    const int warp_n = wid >> 2;
    const int sub    = lane >> 3;
    const int l7     = lane & 7;
    const int bm     = blockIdx.y * BM;
    const int bn     = blockIdx.x * BN;

    const __half* A0 = Ahi + (size_t)bm * DM;
    const __half* A1 = Alo + (size_t)bm * DM;
    const __half* W0 = Whi + (size_t)bn * DM;
    const __half* W1 = Wlo + (size_t)bn * DM;

    float acc[2][8][4];
    #pragma unroll
    for (int i = 0; i < 2; i++)
        #pragma unroll
        for (int j = 0; j < 8; j++)
            #pragma unroll
            for (int c = 0; c < 4; c++) acc[i][j][c] = 0.f;

    const uint32_t a_off =
        ((warp_m * 32 + (l7 | ((sub & 1) << 3))) * SKPG + ((sub >> 1) << 3)) * 2;
    const uint32_t b_off =
        ((warp_n * 64 + (l7 + ((sub >> 1) << 3))) * SKPG + ((sub & 1) << 3)) * 2;

    gemm_issue(sb, 0, 0, A0, A1, W0, W1, t);

    const int NS = DM / BKG;   // 32
    for (int kc = 0; kc < NS; kc++) {
        const int buf = kc & 1;
        if (kc + 1 < NS) {
            gemm_issue(sb, buf ^ 1, (kc + 1) * BKG, A0, A1, W0, W1, t);
            CP_WAIT1();
        } else {
            CP_WAIT0();
        }
        __syncthreads();

        const uint32_t bA  = sb + buf * (GSTAGE_H * 2);
        const uint32_t bAl = bA + GT_H * 2;
        const uint32_t bW  = bA + 2 * GT_H * 2;
        const uint32_t bWl = bA + 3 * GT_H * 2;

        #pragma unroll
        for (int k16 = 0; k16 < 2; k16++) {
            const uint32_t ko = k16 * 32;      // 16 halves = 32B
            uint32_t ah[2][4], al[2][4];
            #pragma unroll
            for (int im = 0; im < 2; im++) {
                uint32_t off = a_off + im * (16 * SKPG * 2) + ko;
                ldm_x4(ah[im], bA + off);
                ldm_x4(al[im], bAl + off);
            }
            #pragma unroll
            for (int jn16 = 0; jn16 < 4; jn16++) {
                uint32_t off = b_off + jn16 * (16 * SKPG * 2) + ko;
                uint32_t rh[4], rl[4];
                ldm_x4(rh, bW + off);
                ldm_x4(rl, bWl + off);
                #pragma unroll
                for (int im = 0; im < 2; im++) {
                    mma16816(acc[im][jn16 * 2], ah[im], rh);
                    mma16816(acc[im][jn16 * 2], ah[im], rl);
                    mma16816(acc[im][jn16 * 2], al[im], rh);
                    mma16816(acc[im][jn16 * 2 + 1], ah[im], rh + 2);
                    mma16816(acc[im][jn16 * 2 + 1], ah[im], rl + 2);
                    mma16816(acc[im][jn16 * 2 + 1], al[im], rh + 2);
                }
            }
        }
        __syncthreads();
    }

    const int g  = lane >> 2;
    const int tc = (lane & 3) * 2;
    #pragma unroll
    for (int im = 0; im < 2; im++) {
        const int r0 = bm + warp_m * 32 + im * 16 + g;
        #pragma unroll
        for (int jn = 0; jn < 8; jn++) {
            const int c = bn + warp_n * 64 + jn * 8 + tc;
            const float b0 = bias[c], b1 = bias[c + 1];
            float v0 = (acc[im][jn][0] + b0) * scale;
            float v1 = (acc[im][jn][1] + b1) * scale;
            float v2 = (acc[im][jn][2] + b0) * scale;
            float v3 = (acc[im][jn][3] + b1) * scale;
            if (Cf) {
                *(float2*)(Cf + (size_t)r0 * DM + c) = make_float2(v0, v1);
                *(float2*)(Cf + (size_t)(r0 + 8) * DM + c) = make_float2(v2, v3);
            } else {
                uint32_t hi, lo;
                split2(v0, v1, hi, lo);
                *(uint32_t*)(Chi + (size_t)r0 * DM + c) = hi;
                *(uint32_t*)(Clo + (size_t)r0 * DM + c) = lo;
                split2(v2, v3, hi, lo);
                *(uint32_t*)(Chi + (size_t)(r0 + 8) * DM + c) = hi;
                *(uint32_t*)(Clo + (size_t)(r0 + 8) * DM + c) = lo;
            }
        }
    }
}

// ---------------- HMMA flash attention with cp.async pipeline ---------------
// Block = 128 q rows x one (b,h). Key chunk = 64, 2 stages.
#define ATK  64
#define ASKP 72
#define AT_H (64 * ASKP)               // halves per tile (4608)
#define ASTAGE_H (4 * AT_H)            // halves per stage (18432)
#define ATTN_SMEM (2 * ASTAGE_H * 2)   // 73728 bytes

__device__ __forceinline__ void attn_issue(uint32_t sb, int buf, int k0,
    const __half* Khb, const __half* Klb, const __half* Vhb, const __half* Vlb,
    int t)
{
    const __half* bases[4] = {Khb, Klb, Vhb, Vlb};
    const uint32_t stb = sb + buf * (ASTAGE_H * 2);
    #pragma unroll
    for (int j = 0; j < 8; j++) {
        const int tile = j >> 1;
        const int r = t + (j & 1) * 256;   // 0..511
        const int row = r >> 3, c16 = r & 7;
        const __half* gp = bases[tile] + (size_t)(k0 + row) * DM + c16 * 8;
        uint32_t sa = stb + (tile * AT_H + row * ASKP + c16 * 8) * 2;
        CP_ASYNC16(sa, gp);
    }
    CP_COMMIT();
}

__global__ __launch_bounds__(256)
void attn_mma(const float* __restrict__ mask)
{
    extern __shared__ __half sh[];
    const uint32_t sb = smem_u32(sh);

    const int t    = threadIdx.x;
    const int lane = t & 31;
    const int wid  = t >> 5;
    const int sub  = lane >> 3;
    const int l7   = lane & 7;
    const int g    = lane >> 2;
    const int c2   = (lane & 3) * 2;

    const int q0 = blockIdx.x * 128;
    const int bh = blockIdx.y;
    const int b  = bh >> 4;
    const int h  = bh & 15;

    const size_t base = (size_t)b * SEQ * DM + h * DEPTH;
    const __half* Qhb = g_Qh + base;
    const __half* Qlb = g_Ql + base;
    const __half* Khb = g_Kh + base;
    const __half* Klb = g_Kl + base;
    const __half* Vhb = g_Vh + base;
    const __half* Vlb = g_Vl + base;

    // ---- stage Q (rows 0-63 -> stage0 K area, rows 64-127 -> stage1) ----
    #pragma unroll
    for (int j = 0; j < 8; j++) {
        const int tensor = j >> 2;            // 0=hi,1=lo
        const int r = t + (j & 3) * 256;      // 0..1023
        const int row = r >> 3, c16 = r & 7;
        const int stage = row >> 6, lrow = row & 63;
        const __half* src = (tensor ? Qlb : Qhb) + (size_t)(q0 + row) * DM
                            + c16 * 8;
        __half* dst = sh + stage * ASTAGE_H + tensor * AT_H + lrow * ASKP
                      + c16 * 8;
        *(uint4*)dst = *(const uint4*)src;
    }
    __syncthreads();

    // ---- Q fragments to registers ----
    uint32_t qh[4][4], ql[4][4];
    {
        const int qrow = wid * 16 + (l7 | ((sub & 1) << 3));
        const uint32_t stb = sb + (qrow >> 6) * (ASTAGE_H * 2);
        const int lrow = qrow & 63;
        #pragma unroll
        for (int kk = 0; kk < 4; kk++) {
            uint32_t off = (lrow * ASKP + ((sub >> 1) << 3) + kk * 16) * 2;
            ldm_x4(qh[kk], stb + off);
            ldm_x4(ql[kk], stb + AT_H * 2 + off);
        }
    }
    __syncthreads();   // all warps done reading Q before cp.async overwrites

    float oacc[8][4];
    #pragma unroll
    for (int j = 0; j < 8; j++)
        #pragma unroll
        for (int c = 0; c < 4; c++) oacc[j][c] = 0.f;
    float rmax[2] = {-1e30f, -1e30f};
    float rsum[2] = {0.f, 0.f};

    const int mrow = q0 + wid * 16 + g;

    attn_issue(sb, 0, 0, Khb, Klb, Vhb, Vlb, t);

    const int NC = SEQ / ATK;   // 16
    for (int kc = 0; kc < NC; kc++) {
        const int buf = kc & 1;
        const int k0 = kc * ATK;
        if (kc + 1 < NC) {
            attn_issue(sb, buf ^ 1, (kc + 1) * ATK, Khb, Klb, Vhb, Vlb, t);
            CP_WAIT1();
        } else {
            CP_WAIT0();
        }
        __syncthreads();

        const uint32_t stb = sb + buf * (ASTAGE_H * 2);
        const uint32_t bKh2 = stb;
        const uint32_t bKl2 = stb + AT_H * 2;
        const uint32_t bVh2 = stb + 2 * AT_H * 2;
        const uint32_t bVl2 = stb + 3 * AT_H * 2;

        // ---- S = Q @ K^T ----
        float sacc[8][4];
        #pragma unroll
        for (int j = 0; j < 8; j++)
            #pragma unroll
            for (int c = 0; c < 4; c++) sacc[j][c] = 0.f;

        #pragma unroll
        for (int kk = 0; kk < 4; kk++) {
            #pragma unroll
            for (int jp = 0; jp < 4; jp++) {
                uint32_t rh[4], rl[4];
                uint32_t off = ((jp * 16 + l7 + ((sub >> 1) << 3)) * ASKP
                                + ((sub & 1) << 3) + kk * 16) * 2;
                ldm_x4(rh, bKh2 + off);
                ldm_x4(rl, bKl2 + off);
                mma16816(sacc[2 * jp],     qh[kk], rh);
                mma16816(sacc[2 * jp],     qh[kk], rl);
                mma16816(sacc[2 * jp],     ql[kk], rh);
                mma16816(sacc[2 * jp + 1], qh[kk], rh + 2);
                mma16816(sacc[2 * jp + 1], qh[kk], rl + 2);
                mma16816(sacc[2 * jp + 1], ql[kk], rh + 2);
            }
        }

        // ---- mask ----
        #pragma unroll
        for (int j = 0; j < 8; j++) {
            int col = k0 + j * 8 + c2;
            float2 m0 = *(const float2*)(mask + (size_t)mrow * SEQ + col);
            float2 m1 = *(const float2*)(mask + (size_t)(mrow + 8) * SEQ + col);
            sacc[j][0] -= 1e9f * m0.x; sacc[j][1] -= 1e9f * m0.y;
            sacc[j][2] -= 1e9f * m1.x; sacc[j][3] -= 1e9f * m1.y;
        }

        // ---- online softmax ----
        #pragma unroll
        for (int r = 0; r < 2; r++) {
            float mx = -1e30f;
            #pragma unroll
            for (int j = 0; j < 8; j++)
                mx = fmaxf(mx, fmaxf(sacc[j][2 * r], sacc[j][2 * r + 1]));
            mx = fmaxf(mx, __shfl_xor_sync(0xffffffffu, mx, 1));
            mx = fmaxf(mx, __shfl_xor_sync(0xffffffffu, mx, 2));
            float nm   = fmaxf(rmax[r], mx);
            float corr = __expf(rmax[r] - nm);
            rmax[r] = nm;
            float ps = 0.f;
            #pragma unroll
            for (int j = 0; j < 8; j++) {
                float p0 = __expf(sacc[j][2 * r] - nm);
                float p1 = __expf(sacc[j][2 * r + 1] - nm);
                sacc[j][2 * r] = p0; sacc[j][2 * r + 1] = p1;
                ps += p0 + p1;
            }
            ps += __shfl_xor_sync(0xffffffffu, ps, 1);
            ps += __shfl_xor_sync(0xffffffffu, ps, 2);
            rsum[r] = rsum[r] * corr + ps;
            #pragma unroll
            for (int jn = 0; jn < 8; jn++) {
                oacc[jn][2 * r]     *= corr;
                oacc[jn][2 * r + 1] *= corr;
            }
        }

        // ---- O += P @ V ----
        #pragma unroll
        for (int kk = 0; kk < 4; kk++) {
            uint32_t ph[4], pl[4];
            split2(sacc[2 * kk][0],     sacc[2 * kk][1],     ph[0], pl[0]);
            split2(sacc[2 * kk][2],     sacc[2 * kk][3],     ph[1], pl[1]);
            split2(sacc[2 * kk + 1][0], sacc[2 * kk + 1][1], ph[2], pl[2]);
            split2(sacc[2 * kk + 1][2], sacc[2 * kk + 1][3], ph[3], pl[3]);
            #pragma unroll
            for (int jd = 0; jd < 4; jd++) {
                uint32_t vh4[4], vl4[4];
                uint32_t off = ((kk * 16 + ((sub & 1) << 3) + l7) * ASKP
                                + jd * 16 + ((sub >> 1) << 3)) * 2;
                ldm_x4_t(vh4, bVh2 + off);
                ldm_x4_t(vl4, bVl2 + off);
                mma16816(oacc[2 * jd],     ph, vh4);
                mma16816(oacc[2 * jd],     ph, vl4);
                mma16816(oacc[2 * jd],     pl, vh4);
                mma16816(oacc[2 * jd + 1], ph, vh4 + 2);
                mma16816(oacc[2 * jd + 1], ph, vl4 + 2);
                mma16816(oacc[2 * jd + 1], pl, vh4 + 2);
            }
        }
        __syncthreads();
    }

    // ---- epilogue: normalize, write fp16 hi/lo ----
    const float inv0 = 1.0f / rsum[0];
    const float inv1 = 1.0f / rsum[1];
    const int orow = q0 + wid * 16 + g;
    __half* Ohb = g_Oh + base + (size_t)orow * DM;
    __half* Olb = g_Ol + base + (size_t)orow * DM;
    #pragma unroll
    for (int jn = 0; jn < 8; jn++) {
        int cc = jn * 8 + c2;
        uint32_t hi, lo;
        split2(oacc[jn][0] * inv0, oacc[jn][1] * inv0, hi, lo);
        *(uint32_t*)(Ohb + cc) = hi;
        *(uint32_t*)(Olb + cc) = lo;
        split2(oacc[jn][2] * inv1, oacc[jn][3] * inv1, hi, lo);
        *(uint32_t*)(Ohb + 8 * DM + cc) = hi;
        *(uint32_t*)(Olb + 8 * DM + cc) = lo;
    }
}

// ---------------------------------------------------------------------------
extern "C" void kernel_launch(void* const* d_in, const int* in_sizes, int n_in,
                              void* d_out, int out_size)
{
    (void)in_sizes; (void)n_in; (void)out_size;
    const float* q    = (const float*)d_in[0];
    const float* k    = (const float*)d_in[1];
    const float* v    = (const float*)d_in[2];
    const float* mask = (const float*)d_in[3];
    const float* wq_w = (const float*)d_in[4];
    const float* wq_b = (const float*)d_in[5];
    const float* wk_w = (const float*)d_in[6];
    const float* wk_b = (const float*)d_in[7];
    const float* wv_w = (const float*)d_in[8];
    const float* wv_b = (const float*)d_in[9];
    const float* pl_w = (const float*)d_in[10];
    const float* pl_b = (const float*)d_in[11];
    float* out = (float*)d_out;

    __half *Qh, *Ql, *Kh, *Kl, *Vh, *Vl, *Oh, *Ol, *xhi, *xlo, *whi, *wlo;
    cudaGetSymbolAddress((void**)&Qh, g_Qh);
    cudaGetSymbolAddress((void**)&Ql, g_Ql);
    cudaGetSymbolAddress((void**)&Kh, g_Kh);
    cudaGetSymbolAddress((void**)&Kl, g_Kl);
    cudaGetSymbolAddress((void**)&Vh, g_Vh);
    cudaGetSymbolAddress((void**)&Vl, g_Vl);
    cudaGetSymbolAddress((void**)&Oh, g_Oh);
    cudaGetSymbolAddress((void**)&Ol, g_Ol);
    cudaGetSymbolAddress((void**)&xhi, g_xhi);
    cudaGetSymbolAddress((void**)&xlo, g_xlo);
    cudaGetSymbolAddress((void**)&whi, g_whi);
    cudaGetSymbolAddress((void**)&wlo, g_wlo);

    cudaFuncSetAttribute(gemm_hmma, cudaFuncAttributeMaxDynamicSharedMemorySize,
                         GEMM_SMEM);
    cudaFuncSetAttribute(attn_mma, cudaFuncAttributeMaxDynamicSharedMemorySize,
                         ATTN_SMEM);

    const int NX = MROWS * DM;
    const int NW = DM * DM;
    dim3 gg(DM / BN, MROWS / BM);   // (8, 32)

    split_f16<<<NX / 1024, 256>>>(q, xhi, xlo, NX);
    split_f16<<<NW / 1024, 256>>>(wq_w, whi, wlo, NW);
    gemm_hmma<<<gg, 256, GEMM_SMEM>>>(xhi, xlo, whi, wlo, wq_b,
                                      nullptr, Qh, Ql, 0.125f);
    split_f16<<<NX / 1024, 256>>>(k, xhi, xlo, NX);
    split_f16<<<NW / 1024, 256>>>(wk_w, whi, wlo, NW);
    gemm_hmma<<<gg, 256, GEMM_SMEM>>>(xhi, xlo, whi, wlo, wk_b,
                                      nullptr, Kh, Kl, 1.0f);
    split_f16<<<NX / 1024, 256>>>(v, xhi, xlo, NX);
    split_f16<<<NW / 1024, 256>>>(wv_w, whi, wlo, NW);
    gemm_hmma<<<gg, 256, GEMM_SMEM>>>(xhi, xlo, whi, wlo, wv_b,
                                      nullptr, Vh, Vl, 1.0f);

    attn_mma<<<dim3(SEQ / 128, BATCH * NHEAD), 256, ATTN_SMEM>>>(mask);

    split_f16<<<NW / 1024, 256>>>(pl_w, whi, wlo, NW);
    gemm_hmma<<<gg, 256, GEMM_SMEM>>>(Oh, Ol, whi, wlo, pl_b,
                                      out, nullptr, nullptr, 1.0f);
}

// round 8
// speedup vs baseline: 2.5294x; 1.0011x over previous
#include <cuda_runtime.h>
#include <cuda_fp16.h>
#include <cstdint>

#define BATCH  4
#define SEQ    1024
#define DM     1024
#define NHEAD  16
#define DEPTH  64
#define MROWS  (BATCH * SEQ)

// ---------------- scratch (device globals; allocation-free rule) ------------
__device__ __half g_Qh[(size_t)MROWS * DM];
__device__ __half g_Ql[(size_t)MROWS * DM];
__device__ __half g_Kh[(size_t)MROWS * DM];
__device__ __half g_Kl[(size_t)MROWS * DM];
__device__ __half g_Vh[(size_t)MROWS * DM];
__device__ __half g_Vl[(size_t)MROWS * DM];
__device__ __half g_Oh[(size_t)MROWS * DM];
__device__ __half g_Ol[(size_t)MROWS * DM];
__device__ __half g_xhi[(size_t)MROWS * DM];
__device__ __half g_xlo[(size_t)MROWS * DM];
__device__ __half g_whi[(size_t)DM * DM];
__device__ __half g_wlo[(size_t)DM * DM];

// ---------------- helpers ----------------------------------------------------
__device__ __forceinline__ uint32_t smem_u32(const void* p) {
    uint32_t a;
    asm("{ .reg .u64 t; cvta.to.shared.u64 t, %1; cvt.u32.u64 %0, t; }"
        : "=r"(a) : "l"(p));
    return a;
}
__device__ __forceinline__ void ldm_x4(uint32_t* r, uint32_t addr) {
    asm volatile("ldmatrix.sync.aligned.m8n8.x4.shared.b16 {%0,%1,%2,%3}, [%4];"
                 : "=r"(r[0]), "=r"(r[1]), "=r"(r[2]), "=r"(r[3]) : "r"(addr));
}
__device__ __forceinline__ void ldm_x4_t(uint32_t* r, uint32_t addr) {
    asm volatile("ldmatrix.sync.aligned.m8n8.x4.trans.shared.b16 {%0,%1,%2,%3}, [%4];"
                 : "=r"(r[0]), "=r"(r[1]), "=r"(r[2]), "=r"(r[3]) : "r"(addr));
}
// NOTE: non-volatile — pure register math, lets ptxas reorder/pipeline MMAs.
__device__ __forceinline__ void mma16816(float* d, const uint32_t* a,
                                         const uint32_t* b) {
    asm("mma.sync.aligned.m16n8k16.row.col.f32.f16.f16.f32 "
        "{%0,%1,%2,%3}, {%4,%5,%6,%7}, {%8,%9}, {%0,%1,%2,%3};"
        : "+f"(d[0]), "+f"(d[1]), "+f"(d[2]), "+f"(d[3])
        : "r"(a[0]), "r"(a[1]), "r"(a[2]), "r"(a[3]), "r"(b[0]), "r"(b[1]));
}
__device__ __forceinline__ void split2(float a, float b, uint32_t& hi,
                                       uint32_t& lo) {
    __half ha = __float2half_rn(a), hb = __float2half_rn(b);
    __half la = __float2half_rn(a - __half2float(ha));
    __half lb = __float2half_rn(b - __half2float(hb));
    hi = (uint32_t)__half_as_ushort(ha) | ((uint32_t)__half_as_ushort(hb) << 16);
    lo = (uint32_t)__half_as_ushort(la) | ((uint32_t)__half_as_ushort(lb) << 16);
}
#define CP_ASYNC16(saddr, gptr) \
    asm volatile("cp.async.cg.shared.global [%0], [%1], 16;" \
                 :: "r"(saddr), "l"(gptr))
#define CP_COMMIT() asm volatile("cp.async.commit_group;")
#define CP_WAIT1()  asm volatile("cp.async.wait_group 1;")
#define CP_WAIT0()  asm volatile("cp.async.wait_group 0;")

// ---------------- fp32 -> fp16 hi/lo split -----------------------------------
__global__ __launch_bounds__(256)
void split_f16(const float* __restrict__ x, __half* __restrict__ hi,
               __half* __restrict__ lo, int n)
{
    int i = (blockIdx.x * 256 + threadIdx.x) * 4;
    if (i >= n) return;
    float4 v = *(const float4*)(x + i);
    float a[4] = {v.x, v.y, v.z, v.w};
    __half h2[4], l2[4];
    #pragma unroll
    for (int j = 0; j < 4; j++) {
        __half h = __float2half_rn(a[j]);
        h2[j] = h;
        l2[j] = __float2half_rn(a[j] - __half2float(h));
    }
    *(uint2*)(hi + i) = *(uint2*)h2;
    *(uint2*)(lo + i) = *(uint2*)l2;
}

// ---------------- HMMA GEMM with cp.async 2-stage pipeline ------------------
#define BM 128
#define BN 128
#define BKG 32
#define SKPG 40
#define GT_H (128 * SKPG)
#define GSTAGE_H (4 * GT_H)
#define GEMM_SMEM (2 * GSTAGE_H * 2) // 81920 bytes

__device__ __forceinline__ void gemm_issue(uint32_t sb, int buf, int k0,
    const __half* A0, const __half* A1, const __half* W0, const __half* W1,
    int t)
{
    const __half* bases[4] = {A0, A1, W0, W1};
    const uint32_t stb = sb + buf * (GSTAGE_H * 2);
    #pragma unroll
    for (int j = 0; j < 8; j++) {
        const int tile = j >> 1;
        const int r = t + (j & 1) * 256;
        const int row = r >> 2, c16 = r & 3;
        const __half* gp = bases[tile] + (size_t)row * DM + k0 + c16 * 8;
        uint32_t sa = stb + (tile * GT_H + row * SKPG + c16 * 8) * 2;
        CP_ASYNC16(sa, gp);
    }
    CP_COMMIT();
}

__global__ void __launch_bounds__(256, 2)
gemm_hmma(const __half* __restrict__ Ahi, const __half* __restrict__ Alo,
          const __half* __restrict__ Whi, const __half* __restrict__ Wlo,
          const float* __restrict__ bias,
          float* __restrict__ Cf, __half* __restrict__ Chi,
          __half* __restrict__ Clo, float scale)
{
    extern __shared__ __half sh[];
    const uint32_t sb = smem_u32(sh);

    const int t      = threadIdx.x;
    const int lane   = t & 31;
    const int wid    = t >> 5;
    const int warp_m = wid & 3;
    const int warp_n = wid >> 2;
    const int sub    = lane >> 3;
    const int l7     = lane & 7;
    const int bm     = blockIdx.y * BM;
    const int bn     = blockIdx.x * BN;

    const __half* A0 = Ahi + (size_t)bm * DM;
    const __half* A1 = Alo + (size_t)bm * DM;
    const __half* W0 = Whi + (size_t)bn * DM;
    const __half* W1 = Wlo + (size_t)bn * DM;

    float acc[2][8][4];
    #pragma unroll
    for (int i = 0; i < 2; i++)
        #pragma unroll
        for (int j = 0; j < 8; j++)
            #pragma unroll
            for (int c = 0; c < 4; c++) acc[i][j][c] = 0.f;

    const uint32_t a_off =
        ((warp_m * 32 + (l7 | ((sub & 1) << 3))) * SKPG + ((sub >> 1) << 3)) * 2;
    const uint32_t b_off =
        ((warp_n * 64 + (l7 + ((sub >> 1) << 3))) * SKPG + ((sub & 1) << 3)) * 2;

    gemm_issue(sb, 0, 0, A0, A1, W0, W1, t);

    const int NS = DM / BKG;   // 32
    for (int kc = 0; kc < NS; kc++) {
        const int buf = kc & 1;
        if (kc + 1 < NS) {
            gemm_issue(sb, buf ^ 1, (kc + 1) * BKG, A0, A1, W0, W1, t);
            CP_WAIT1();
        } else {
            CP_WAIT0();
        }
        __syncthreads();

        const uint32_t bA  = sb + buf * (GSTAGE_H * 2);
        const uint32_t bAl = bA + GT_H * 2;
        const uint32_t bW  = bA + 2 * GT_H * 2;
        const uint32_t bWl = bA + 3 * GT_H * 2;

        #pragma unroll
        for (int k16 = 0; k16 < 2; k16++) {
            const uint32_t ko = k16 * 32;
            uint32_t ah[2][4], al[2][4];
            #pragma unroll
            for (int im = 0; im < 2; im++) {
                uint32_t off = a_off + im * (16 * SKPG * 2) + ko;
                ldm_x4(ah[im], bA + off);
                ldm_x4(al[im], bAl + off);
            }
            #pragma unroll
            for (int jn16 = 0; jn16 < 4; jn16++) {
                uint32_t off = b_off + jn16 * (16 * SKPG * 2) + ko;
                uint32_t rh[4], rl[4];
                ldm_x4(rh, bW + off);
                ldm_x4(rl, bWl + off);
                float* a00 = acc[0][jn16 * 2];
                float* a10 = acc[1][jn16 * 2];
                float* a01 = acc[0][jn16 * 2 + 1];
                float* a11 = acc[1][jn16 * 2 + 1];
                // pass 1: Ahi x Whi  (4 independent accumulators)
                mma16816(a00, ah[0], rh);
                mma16816(a10, ah[1], rh);
                mma16816(a01, ah[0], rh + 2);
                mma16816(a11, ah[1], rh + 2);
                // pass 2: Ahi x Wlo
                mma16816(a00, ah[0], rl);
                mma16816(a10, ah[1], rl);
                mma16816(a01, ah[0], rl + 2);
                mma16816(a11, ah[1], rl + 2);
                // pass 3: Alo x Whi
                mma16816(a00, al[0], rh);
                mma16816(a10, al[1], rh);
                mma16816(a01, al[0], rh + 2);
                mma16816(a11, al[1], rh + 2);
            }
        }
        __syncthreads();
    }

    const int g  = lane >> 2;
    const int tc = (lane & 3) * 2;
    #pragma unroll
    for (int im = 0; im < 2; im++) {
        const int r0 = bm + warp_m * 32 + im * 16 + g;
        #pragma unroll
        for (int jn = 0; jn < 8; jn++) {
            const int c = bn + warp_n * 64 + jn * 8 + tc;
            const float b0 = bias[c], b1 = bias[c + 1];
            float v0 = (acc[im][jn][0] + b0) * scale;
            float v1 = (acc[im][jn][1] + b1) * scale;
            float v2 = (acc[im][jn][2] + b0) * scale;
            float v3 = (acc[im][jn][3] + b1) * scale;
            if (Cf) {
                *(float2*)(Cf + (size_t)r0 * DM + c) = make_float2(v0, v1);
                *(float2*)(Cf + (size_t)(r0 + 8) * DM + c) = make_float2(v2, v3);
            } else {
                uint32_t hi, lo;
                split2(v0, v1, hi, lo);
                *(uint32_t*)(Chi + (size_t)r0 * DM + c) = hi;
                *(uint32_t*)(Clo + (size_t)r0 * DM + c) = lo;
                split2(v2, v3, hi, lo);
                *(uint32_t*)(Chi + (size_t)(r0 + 8) * DM + c) = hi;
                *(uint32_t*)(Clo + (size_t)(r0 + 8) * DM + c) = lo;
            }
        }
    }
}

// ---------------- HMMA flash attention with cp.async pipeline ---------------
#define ATK  64
#define ASKP 72
#define AT_H (64 * ASKP)
#define ASTAGE_H (4 * AT_H)
#define ATTN_SMEM (2 * ASTAGE_H * 2)   // 73728 bytes

__device__ __forceinline__ void attn_issue(uint32_t sb, int buf, int k0,
    const __half* Khb, const __half* Klb, const __half* Vhb, const __half* Vlb,
    int t)
{
    const __half* bases[4] = {Khb, Klb, Vhb, Vlb};
    const uint32_t stb = sb + buf * (ASTAGE_H * 2);
    #pragma unroll
    for (int j = 0; j < 8; j++) {
        const int tile = j >> 1;
        const int r = t + (j & 1) * 256;
        const int row = r >> 3, c16 = r & 7;
        const __half* gp = bases[tile] + (size_t)(k0 + row) * DM + c16 * 8;
        uint32_t sa = stb + (tile * AT_H + row * ASKP + c16 * 8) * 2;
        CP_ASYNC16(sa, gp);
    }
    CP_COMMIT();
}

__global__ __launch_bounds__(256)
void attn_mma(const float* __restrict__ mask)
{
    extern __shared__ __half sh[];
    const uint32_t sb = smem_u32(sh);

    const int t    = threadIdx.x;
    const int lane = t & 31;
    const int wid  = t >> 5;
    const int sub  = lane >> 3;
    const int l7   = lane & 7;
    const int g    = lane >> 2;
    const int c2   = (lane & 3) * 2;

    const int q0 = blockIdx.x * 128;
    const int bh = blockIdx.y;
    const int b  = bh >> 4;
    const int h  = bh & 15;

    const size_t base = (size_t)b * SEQ * DM + h * DEPTH;
    const __half* Qhb = g_Qh + base;
    const __half* Qlb = g_Ql + base;
    const __half* Khb = g_Kh + base;
    const __half* Klb = g_Kl + base;
    const __half* Vhb = g_Vh + base;
    const __half* Vlb = g_Vl + base;

    // ---- stage Q (rows 0-63 -> stage0 K area, rows 64-127 -> stage1) ----
    #pragma unroll
    for (int j = 0; j < 8; j++) {
        const int tensor = j >> 2;
        const int r = t + (j & 3) * 256;
        const int row = r >> 3, c16 = r & 7;
        const int stage = row >> 6, lrow = row & 63;
        const __half* src = (tensor ? Qlb : Qhb) + (size_t)(q0 + row) * DM
                            + c16 * 8;
        __half* dst = sh + stage * ASTAGE_H + tensor * AT_H + lrow * ASKP
                      + c16 * 8;
        *(uint4*)dst = *(const uint4*)src;
    }
    __syncthreads();

    uint32_t qh[4][4], ql[4][4];
    {
        const int qrow = wid * 16 + (l7 | ((sub & 1) << 3));
        const uint32_t stb = sb + (qrow >> 6) * (ASTAGE_H * 2);
        const int lrow = qrow & 63;
        #pragma unroll
        for (int kk = 0; kk < 4; kk++) {
            uint32_t off = (lrow * ASKP + ((sub >> 1) << 3) + kk * 16) * 2;
            ldm_x4(qh[kk], stb + off);
            ldm_x4(ql[kk], stb + AT_H * 2 + off);
        }
    }
    __syncthreads();

    float oacc[8][4];
    #pragma unroll
    for (int j = 0; j < 8; j++)
        #pragma unroll
        for (int c = 0; c < 4; c++) oacc[j][c] = 0.f;
    float rmax[2] = {-1e30f, -1e30f};
    float rsum[2] = {0.f, 0.f};

    const int mrow = q0 + wid * 16 + g;

    attn_issue(sb, 0, 0, Khb, Klb, Vhb, Vlb, t);

    const int NC = SEQ / ATK;   // 16
    for (int kc = 0; kc < NC; kc++) {
        const int buf = kc & 1;
        const int k0 = kc * ATK;
        if (kc + 1 < NC) {
            attn_issue(sb, buf ^ 1, (kc + 1) * ATK, Khb, Klb, Vhb, Vlb, t);
            CP_WAIT1();
        } else {
            CP_WAIT0();
        }
        __syncthreads();

        const uint32_t stb = sb + buf * (ASTAGE_H * 2);
        const uint32_t bKh2 = stb;
        const uint32_t bKl2 = stb + AT_H * 2;
        const uint32_t bVh2 = stb + 2 * AT_H * 2;
        const uint32_t bVl2 = stb + 3 * AT_H * 2;

        // ---- S = Q @ K^T (accumulator-interleaved issue order) ----
        float sacc[8][4];
        #pragma unroll
        for (int j = 0; j < 8; j++)
            #pragma unroll
            for (int c = 0; c < 4; c++) sacc[j][c] = 0.f;

        #pragma unroll
        for (int kk = 0; kk < 4; kk++) {
            #pragma unroll
            for (int jp = 0; jp < 4; jp++) {
                uint32_t rh[4], rl[4];
                uint32_t off = ((jp * 16 + l7 + ((sub >> 1) << 3)) * ASKP
                                + ((sub & 1) << 3) + kk * 16) * 2;
                ldm_x4(rh, bKh2 + off);
                ldm_x4(rl, bKl2 + off);
                float* s0 = sacc[2 * jp];
                float* s1 = sacc[2 * jp + 1];
                mma16816(s0, qh[kk], rh);
                mma16816(s1, qh[kk], rh + 2);
                mma16816(s0, qh[kk], rl);
                mma16816(s1, qh[kk], rl + 2);
                mma16816(s0, ql[kk], rh);
                mma16816(s1, ql[kk], rh + 2);
            }
        }

        // ---- mask ----
        #pragma unroll
        for (int j = 0; j < 8; j++) {
            int col = k0 + j * 8 + c2;
            float2 m0 = *(const float2*)(mask + (size_t)mrow * SEQ + col);
            float2 m1 = *(const float2*)(mask + (size_t)(mrow + 8) * SEQ + col);
            sacc[j][0] -= 1e9f * m0.x; sacc[j][1] -= 1e9f * m0.y;
            sacc[j][2] -= 1e9f * m1.x; sacc[j][3] -= 1e9f * m1.y;
        }

        // ---- online softmax ----
        #pragma unroll
        for (int r = 0; r < 2; r++) {
            float mx = -1e30f;
            #pragma unroll
            for (int j = 0; j < 8; j++)
                mx = fmaxf(mx, fmaxf(sacc[j][2 * r], sacc[j][2 * r + 1]));
            mx = fmaxf(mx, __shfl_xor_sync(0xffffffffu, mx, 1));
            mx = fmaxf(mx, __shfl_xor_sync(0xffffffffu, mx, 2));
            float nm   = fmaxf(rmax[r], mx);
            float corr = __expf(rmax[r] - nm);
            rmax[r] = nm;
            float ps = 0.f;
            #pragma unroll
            for (int j = 0; j < 8; j++) {
                float p0 = __expf(sacc[j][2 * r] - nm);
                float p1 = __expf(sacc[j][2 * r + 1] - nm);
                sacc[j][2 * r] = p0; sacc[j][2 * r + 1] = p1;
                ps += p0 + p1;
            }
            ps += __shfl_xor_sync(0xffffffffu, ps, 1);
            ps += __shfl_xor_sync(0xffffffffu, ps, 2);
            rsum[r] = rsum[r] * corr + ps;
            #pragma unroll
            for (int jn = 0; jn < 8; jn++) {
                oacc[jn][2 * r]     *= corr;
                oacc[jn][2 * r + 1] *= corr;
            }
        }

        // ---- O += P @ V (accumulator-interleaved issue order) ----
        #pragma unroll
        for (int kk = 0; kk < 4; kk++) {
            uint32_t ph[4], pl[4];
            split2(sacc[2 * kk][0],     sacc[2 * kk][1],     ph[0], pl[0]);
            split2(sacc[2 * kk][2],     sacc[2 * kk][3],     ph[1], pl[1]);
            split2(sacc[2 * kk + 1][0], sacc[2 * kk + 1][1], ph[2], pl[2]);
            split2(sacc[2 * kk + 1][2], sacc[2 * kk + 1][3], ph[3], pl[3]);
            #pragma unroll
            for (int jd = 0; jd < 4; jd++) {
                uint32_t vh4[4], vl4[4];
                uint32_t off = ((kk * 16 + ((sub & 1) << 3) + l7) * ASKP
                                + jd * 16 + ((sub >> 1) << 3)) * 2;
                ldm_x4_t(vh4, bVh2 + off);
                ldm_x4_t(vl4, bVl2 + off);
                float* o0 = oacc[2 * jd];
                float* o1 = oacc[2 * jd + 1];
                mma16816(o0, ph, vh4);
                mma16816(o1, ph, vh4 + 2);
                mma16816(o0, ph, vl4);
                mma16816(o1, ph, vl4 + 2);
                mma16816(o0, pl, vh4);
                mma16816(o1, pl, vh4 + 2);
            }
        }
        __syncthreads();
    }

    // ---- epilogue: normalize, write fp16 hi/lo ----
    const float inv0 = 1.0f / rsum[0];
    const float inv1 = 1.0f / rsum[1];
    const int orow = q0 + wid * 16 + g;
    __half* Ohb = g_Oh + base + (size_t)orow * DM;
    __half* Olb = g_Ol + base + (size_t)orow * DM;
    #pragma unroll
    for (int jn = 0; jn < 8; jn++) {
        int cc = jn * 8 + c2;
        uint32_t hi, lo;
        split2(oacc[jn][0] * inv0, oacc[jn][1] * inv0, hi, lo);
        *(uint32_t*)(Ohb + cc) = hi;
        *(uint32_t*)(Olb + cc) = lo;
        split2(oacc[jn][2] * inv1, oacc[jn][3] * inv1, hi, lo);
        *(uint32_t*)(Ohb + 8 * DM + cc) = hi;
        *(uint32_t*)(Olb + 8 * DM + cc) = lo;
    }
}

// ---------------------------------------------------------------------------
extern "C" void kernel_launch(void* const* d_in, const int* in_sizes, int n_in,
                              void* d_out, int out_size)
{
    (void)in_sizes; (void)n_in; (void)out_size;
    const float* q    = (const float*)d_in[0];
    const float* k    = (const float*)d_in[1];
    const float* v    = (const float*)d_in[2];
    const float* mask = (const float*)d_in[3];
    const float* wq_w = (const float*)d_in[4];
    const float* wq_b = (const float*)d_in[5];
    const float* wk_w = (const float*)d_in[6];
    const float* wk_b = (const float*)d_in[7];
    const float* wv_w = (const float*)d_in[8];
    const float* wv_b = (const float*)d_in[9];
    const float* pl_w = (const float*)d_in[10];
    const float* pl_b = (const float*)d_in[11];
    float* out = (float*)d_out;

    __half *Qh, *Ql, *Kh, *Kl, *Vh, *Vl, *Oh, *Ol, *xhi, *xlo, *whi, *wlo;
    cudaGetSymbolAddress((void**)&Qh, g_Qh);
    cudaGetSymbolAddress((void**)&Ql, g_Ql);
    cudaGetSymbolAddress((void**)&Kh, g_Kh);
    cudaGetSymbolAddress((void**)&Kl, g_Kl);
    cudaGetSymbolAddress((void**)&Vh, g_Vh);
    cudaGetSymbolAddress((void**)&Vl, g_Vl);
    cudaGetSymbolAddress((void**)&Oh, g_Oh);
    cudaGetSymbolAddress((void**)&Ol, g_Ol);
    cudaGetSymbolAddress((void**)&xhi, g_xhi);
    cudaGetSymbolAddress((void**)&xlo, g_xlo);
    cudaGetSymbolAddress((void**)&whi, g_whi);
    cudaGetSymbolAddress((void**)&wlo, g_wlo);

    cudaFuncSetAttribute(gemm_hmma, cudaFuncAttributeMaxDynamicSharedMemorySize,
                         GEMM_SMEM);
    cudaFuncSetAttribute(attn_mma, cudaFuncAttributeMaxDynamicSharedMemorySize,
                         ATTN_SMEM);

    const int NX = MROWS * DM;
    const int NW = DM * DM;
    dim3 gg(DM / BN, MROWS / BM);   // (8, 32)

    split_f16<<<NX / 1024, 256>>>(q, xhi, xlo, NX);
    split_f16<<<NW / 1024, 256>>>(wq_w, whi, wlo, NW);
    gemm_hmma<<<gg, 256, GEMM_SMEM>>>(xhi, xlo, whi, wlo, wq_b,
                                      nullptr, Qh, Ql, 0.125f);
    split_f16<<<NX / 1024, 256>>>(k, xhi, xlo, NX);
    split_f16<<<NW / 1024, 256>>>(wk_w, whi, wlo, NW);
    gemm_hmma<<<gg, 256, GEMM_SMEM>>>(xhi, xlo, whi, wlo, wk_b,
                                      nullptr, Kh, Kl, 1.0f);
    split_f16<<<NX / 1024, 256>>>(v, xhi, xlo, NX);
    split_f16<<<NW / 1024, 256>>>(wv_w, whi, wlo, NW);
    gemm_hmma<<<gg, 256, GEMM_SMEM>>>(xhi, xlo, whi, wlo, wv_b,
                                      nullptr, Vh, Vl, 1.0f);

    attn_mma<<<dim3(SEQ / 128, BATCH * NHEAD), 256, ATTN_SMEM>>>(mask);

    split_f16<<<NW / 1024, 256>>>(pl_w, whi, wlo, NW);
    gemm_hmma<<<gg, 256, GEMM_SMEM>>>(Oh, Ol, whi, wlo, pl_b,
                                      out, nullptr, nullptr, 1.0f);
}

// round 9
// speedup vs baseline: 2.8619x; 1.1314x over previous
#include <cuda_runtime.h>
#include <cuda_fp16.h>
#include <cstdint>

#define BATCH  4
#define SEQ    1024
#define DM     1024
#define NHEAD  16
#define DEPTH  64
#define MROWS  (BATCH * SEQ)

// ---------------- scratch (device globals; allocation-free rule) ------------
__device__ __half g_Qh[(size_t)MROWS * DM];
__device__ __half g_Ql[(size_t)MROWS * DM];
__device__ __half g_Kh[(size_t)MROWS * DM];
__device__ __half g_Kl[(size_t)MROWS * DM];
__device__ __half g_Vh[(size_t)MROWS * DM];
__device__ __half g_Vl[(size_t)MROWS * DM];
__device__ __half g_Oh[(size_t)MROWS * DM];
__device__ __half g_Ol[(size_t)MROWS * DM];
__device__ __half g_xhi[(size_t)MROWS * DM];
__device__ __half g_xlo[(size_t)MROWS * DM];
__device__ __half g_whi[(size_t)DM * DM];
__device__ __half g_wlo[(size_t)DM * DM];

// ---------------- helpers ----------------------------------------------------
__device__ __forceinline__ uint32_t smem_u32(const void* p) {
    uint32_t a;
    asm("{ .reg .u64 t; cvta.to.shared.u64 t, %1; cvt.u32.u64 %0, t; }"
        : "=r"(a) : "l"(p));
    return a;
}
__device__ __forceinline__ void ldm_x4(uint32_t* r, uint32_t addr) {
    asm volatile("ldmatrix.sync.aligned.m8n8.x4.shared.b16 {%0,%1,%2,%3}, [%4];"
                 : "=r"(r[0]), "=r"(r[1]), "=r"(r[2]), "=r"(r[3]) : "r"(addr));
}
__device__ __forceinline__ void ldm_x4_t(uint32_t* r, uint32_t addr) {
    asm volatile("ldmatrix.sync.aligned.m8n8.x4.trans.shared.b16 {%0,%1,%2,%3}, [%4];"
                 : "=r"(r[0]), "=r"(r[1]), "=r"(r[2]), "=r"(r[3]) : "r"(addr));
}
__device__ __forceinline__ void mma16816(float* d, const uint32_t* a,
                                         const uint32_t* b) {
    asm("mma.sync.aligned.m16n8k16.row.col.f32.f16.f16.f32 "
        "{%0,%1,%2,%3}, {%4,%5,%6,%7}, {%8,%9}, {%0,%1,%2,%3};"
        : "+f"(d[0]), "+f"(d[1]), "+f"(d[2]), "+f"(d[3])
        : "r"(a[0]), "r"(a[1]), "r"(a[2]), "r"(a[3]), "r"(b[0]), "r"(b[1]));
}
__device__ __forceinline__ void split2(float a, float b, uint32_t& hi,
                                       uint32_t& lo) {
    __half ha = __float2half_rn(a), hb = __float2half_rn(b);
    __half la = __float2half_rn(a - __half2float(ha));
    __half lb = __float2half_rn(b - __half2float(hb));
    hi = (uint32_t)__half_as_ushort(ha) | ((uint32_t)__half_as_ushort(hb) << 16);
    lo = (uint32_t)__half_as_ushort(la) | ((uint32_t)__half_as_ushort(lb) << 16);
}
#define CP_ASYNC16(saddr, gptr) \
    asm volatile("cp.async.cg.shared.global [%0], [%1], 16;" \
                 :: "r"(saddr), "l"(gptr))
#define CP_COMMIT() asm volatile("cp.async.commit_group;")
#define CP_WAIT1()  asm volatile("cp.async.wait_group 1;")
#define CP_WAIT0()  asm volatile("cp.async.wait_group 0;")

// ---------------- fp32 -> fp16 hi/lo split -----------------------------------
__global__ __launch_bounds__(256)
void split_f16(const float* __restrict__ x, __half* __restrict__ hi,
               __half* __restrict__ lo, int n)
{
    int i = (blockIdx.x * 256 + threadIdx.x) * 4;
    if (i >= n) return;
    float4 v = *(const float4*)(x + i);
    float a[4] = {v.x, v.y, v.z, v.w};
    __half h2[4], l2[4];
    #pragma unroll
    for (int j = 0; j < 4; j++) {
        __half h = __float2half_rn(a[j]);
        h2[j] = h;
        l2[j] = __float2half_rn(a[j] - __half2float(h));
    }
    *(uint2*)(hi + i) = *(uint2*)h2;
    *(uint2*)(lo + i) = *(uint2*)l2;
}

// ---------------- HMMA GEMM with cp.async 2-stage pipeline ------------------
#define BM 128
#define BN 128
#define BKG 32
#define SKPG 40
#define GT_H (128 * SKPG)
#define GSTAGE_H (4 * GT_H)
#define GEMM_SMEM (2 * GSTAGE_H * 2) // 81920 bytes

__device__ __forceinline__ void gemm_issue(uint32_t sb, int buf, int k0,
    const __half* A0, const __half* A1, const __half* W0, const __half* W1,
    int t)
{
    const __half* bases[4] = {A0, A1, W0, W1};
    const uint32_t stb = sb + buf * (GSTAGE_H * 2);
    #pragma unroll
    for (int j = 0; j < 8; j++) {
        const int tile = j >> 1;
        const int r = t + (j & 1) * 256;
        const int row = r >> 2, c16 = r & 3;
        const __half* gp = bases[tile] + (size_t)row * DM + k0 + c16 * 8;
        uint32_t sa = stb + (tile * GT_H + row * SKPG + c16 * 8) * 2;
        CP_ASYNC16(sa, gp);
    }
    CP_COMMIT();
}

__global__ void __launch_bounds__(256, 2)
gemm_hmma(const __half* __restrict__ Ahi, const __half* __restrict__ Alo,
          const __half* __restrict__ Whi, const __half* __restrict__ Wlo,
          const float* __restrict__ bias,
          float* __restrict__ Cf, __half* __restrict__ Chi,
          __half* __restrict__ Clo, float scale)
{
    extern __shared__ __half sh[];
    const uint32_t sb = smem_u32(sh);

    const int t      = threadIdx.x;
    const int lane   = t & 31;
    const int wid    = t >> 5;
    const int warp_m = wid & 3;
    const int warp_n = wid >> 2;
    const int sub    = lane >> 3;
    const int l7     = lane & 7;
    const int bm     = blockIdx.y * BM;
    const int bn     = blockIdx.x * BN;

    const __half* A0 = Ahi + (size_t)bm * DM;
    const __half* A1 = Alo + (size_t)bm * DM;
    const __half* W0 = Whi + (size_t)bn * DM;
    const __half* W1 = Wlo + (size_t)bn * DM;

    float acc[2][8][4];
    #pragma unroll
    for (int i = 0; i < 2; i++)
        #pragma unroll
        for (int j = 0; j < 8; j++)
            #pragma unroll
            for (int c = 0; c < 4; c++) acc[i][j][c] = 0.f;

    const uint32_t a_off =
        ((warp_m * 32 + (l7 | ((sub & 1) << 3))) * SKPG + ((sub >> 1) << 3)) * 2;
    const uint32_t b_off =
        ((warp_n * 64 + (l7 + ((sub >> 1) << 3))) * SKPG + ((sub & 1) << 3)) * 2;

    gemm_issue(sb, 0, 0, A0, A1, W0, W1, t);

    const int NS = DM / BKG;   // 32
    for (int kc = 0; kc < NS; kc++) {
        const int buf = kc & 1;
        if (kc + 1 < NS) {
            gemm_issue(sb, buf ^ 1, (kc + 1) * BKG, A0, A1, W0, W1, t);
            CP_WAIT1();
        } else {
            CP_WAIT0();
        }
        __syncthreads();

        const uint32_t bA  = sb + buf * (GSTAGE_H * 2);
        const uint32_t bAl = bA + GT_H * 2;
        const uint32_t bW  = bA + 2 * GT_H * 2;
        const uint32_t bWl = bA + 3 * GT_H * 2;

        #pragma unroll
        for (int k16 = 0; k16 < 2; k16++) {
            const uint32_t ko = k16 * 32;
            uint32_t ah[2][4], al[2][4];
            #pragma unroll
            for (int im = 0; im < 2; im++) {
                uint32_t off = a_off + im * (16 * SKPG * 2) + ko;
                ldm_x4(ah[im], bA + off);
                ldm_x4(al[im], bAl + off);
            }
            #pragma unroll
            for (int jn16 = 0; jn16 < 4; jn16++) {
                uint32_t off = b_off + jn16 * (16 * SKPG * 2) + ko;
                uint32_t rh[4], rl[4];
                ldm_x4(rh, bW + off);
                ldm_x4(rl, bWl + off);
                float* a00 = acc[0][jn16 * 2];
                float* a10 = acc[1][jn16 * 2];
                float* a01 = acc[0][jn16 * 2 + 1];
                float* a11 = acc[1][jn16 * 2 + 1];
                mma16816(a00, ah[0], rh);
                mma16816(a10, ah[1], rh);
                mma16816(a01, ah[0], rh + 2);
                mma16816(a11, ah[1], rh + 2);
                mma16816(a00, ah[0], rl);
                mma16816(a10, ah[1], rl);
                mma16816(a01, ah[0], rl + 2);
                mma16816(a11, ah[1], rl + 2);
                mma16816(a00, al[0], rh);
                mma16816(a10, al[1], rh);
                mma16816(a01, al[0], rh + 2);
                mma16816(a11, al[1], rh + 2);
            }
        }
        __syncthreads();
    }

    const int g  = lane >> 2;
    const int tc = (lane & 3) * 2;
    #pragma unroll
    for (int im = 0; im < 2; im++) {
        const int r0 = bm + warp_m * 32 + im * 16 + g;
        #pragma unroll
        for (int jn = 0; jn < 8; jn++) {
            const int c = bn + warp_n * 64 + jn * 8 + tc;
            const float b0 = bias[c], b1 = bias[c + 1];
            float v0 = (acc[im][jn][0] + b0) * scale;
            float v1 = (acc[im][jn][1] + b1) * scale;
            float v2 = (acc[im][jn][2] + b0) * scale;
            float v3 = (acc[im][jn][3] + b1) * scale;
            if (Cf) {
                *(float2*)(Cf + (size_t)r0 * DM + c) = make_float2(v0, v1);
                *(float2*)(Cf + (size_t)(r0 + 8) * DM + c) = make_float2(v2, v3);
            } else {
                uint32_t hi, lo;
                split2(v0, v1, hi, lo);
                *(uint32_t*)(Chi + (size_t)r0 * DM + c) = hi;
                *(uint32_t*)(Clo + (size_t)r0 * DM + c) = lo;
                split2(v2, v3, hi, lo);
                *(uint32_t*)(Chi + (size_t)(r0 + 8) * DM + c) = hi;
                *(uint32_t*)(Clo + (size_t)(r0 + 8) * DM + c) = lo;
            }
        }
    }
}

// ---------------- HMMA flash attention, slim 2-pass variant ------------------
// Block = 128 q rows x one (b,h). Key chunk 64, 2 cp.async stages.
// Tiles per stage: Kh, Vh only (K and V rounded to fp16 in one term each):
//   S = Qh*Kh + Ql*Kh        (K fp16-rounded)
//   O = Ph*Vh + Pl*Vh        (V fp16-rounded)
#define ATK  64
#define ASKP 72
#define AT_H (64 * ASKP)               // halves per tile (4608)
#define ASTAGE_H (2 * AT_H)            // halves per stage (9216)
#define ATTN_SMEM (2 * ASTAGE_H * 2)   // 36864 bytes

__device__ __forceinline__ void attn_issue(uint32_t sb, int buf, int k0,
    const __half* Khb, const __half* Vhb, int t)
{
    const uint32_t stb = sb + buf * (ASTAGE_H * 2);
    #pragma unroll
    for (int j = 0; j < 4; j++) {
        const int tile = j >> 1;           // 0=Kh, 1=Vh
        const int r = t + (j & 1) * 256;   // 0..511
        const int row = r >> 3, c16 = r & 7;
        const __half* gp = (tile ? Vhb : Khb) + (size_t)(k0 + row) * DM
                           + c16 * 8;
        uint32_t sa = stb + (tile * AT_H + row * ASKP + c16 * 8) * 2;
        CP_ASYNC16(sa, gp);
    }
    CP_COMMIT();
}

__global__ void __launch_bounds__(256, 2)
attn_mma(const float* __restrict__ mask)
{
    extern __shared__ __half sh[];
    const uint32_t sb = smem_u32(sh);

    const int t    = threadIdx.x;
    const int lane = t & 31;
    const int wid  = t >> 5;
    const int sub  = lane >> 3;
    const int l7   = lane & 7;
    const int g    = lane >> 2;
    const int c2   = (lane & 3) * 2;

    const int q0 = blockIdx.x * 128;
    const int bh = blockIdx.y;
    const int b  = bh >> 4;
    const int h  = bh & 15;

    const size_t base = (size_t)b * SEQ * DM + h * DEPTH;
    const __half* Qhb = g_Qh + base;
    const __half* Qlb = g_Ql + base;
    const __half* Khb = g_Kh + base;
    const __half* Vhb = g_Vh + base;

    // ---- stage Q: hi -> stage0 area, lo -> stage1 area ----
    #pragma unroll
    for (int j = 0; j < 8; j++) {
        const int tensor = j >> 2;            // 0=hi,1=lo
        const int r = t + (j & 3) * 256;      // 0..1023
        const int row = r >> 3, c16 = r & 7;
        const __half* src = (tensor ? Qlb : Qhb) + (size_t)(q0 + row) * DM
                            + c16 * 8;
        __half* dst = sh + tensor * ASTAGE_H + (row >> 6) * AT_H
                      + (row & 63) * ASKP + c16 * 8;
        *(uint4*)dst = *(const uint4*)src;
    }
    __syncthreads();

    uint32_t qh[4][4], ql[4][4];
    {
        const int qrow = wid * 16 + (l7 | ((sub & 1) << 3));
        const uint32_t hb = sb + ((qrow >> 6) * AT_H + (qrow & 63) * ASKP) * 2;
        #pragma unroll
        for (int kk = 0; kk < 4; kk++) {
            uint32_t off = (((sub >> 1) << 3) + kk * 16) * 2;
            ldm_x4(qh[kk], hb + off);
            ldm_x4(ql[kk], hb + ASTAGE_H * 2 + off);
        }
    }
    __syncthreads();

    float oacc[8][4];
    #pragma unroll
    for (int j = 0; j < 8; j++)
        #pragma unroll
        for (int c = 0; c < 4; c++) oacc[j][c] = 0.f;
    float rmax[2] = {-1e30f, -1e30f};
    float rsum[2] = {0.f, 0.f};

    const int mrow = q0 + wid * 16 + g;

    attn_issue(sb, 0, 0, Khb, Vhb, t);

    const int NC = SEQ / ATK;   // 16
    for (int kc = 0; kc < NC; kc++) {
        const int buf = kc & 1;
        const int k0 = kc * ATK;
        if (kc + 1 < NC) {
            attn_issue(sb, buf ^ 1, (kc + 1) * ATK, Khb, Vhb, t);
            CP_WAIT1();
        } else {
            CP_WAIT0();
        }
        __syncthreads();

        const uint32_t stb  = sb + buf * (ASTAGE_H * 2);
        const uint32_t bKh2 = stb;
        const uint32_t bVh2 = stb + AT_H * 2;

        // ---- S = Qh K^T + Ql K^T ----
        float sacc[8][4];
        #pragma unroll
        for (int j = 0; j < 8; j++)
            #pragma unroll
            for (int c = 0; c < 4; c++) sacc[j][c] = 0.f;

        #pragma unroll
        for (int kk = 0; kk < 4; kk++) {
            #pragma unroll
            for (int jp = 0; jp < 4; jp++) {
                uint32_t rh[4];
                uint32_t off = ((jp * 16 + l7 + ((sub >> 1) << 3)) * ASKP
                                + ((sub & 1) << 3) + kk * 16) * 2;
                ldm_x4(rh, bKh2 + off);
                float* s0 = sacc[2 * jp];
                float* s1 = sacc[2 * jp + 1];
                mma16816(s0, qh[kk], rh);
                mma16816(s1, qh[kk], rh + 2);
                mma16816(s0, ql[kk], rh);
                mma16816(s1, ql[kk], rh + 2);
            }
        }

        // ---- mask ----
        #pragma unroll
        for (int j = 0; j < 8; j++) {
            int col = k0 + j * 8 + c2;
            float2 m0 = *(const float2*)(mask + (size_t)mrow * SEQ + col);
            float2 m1 = *(const float2*)(mask + (size_t)(mrow + 8) * SEQ + col);
            sacc[j][0] -= 1e9f * m0.x; sacc[j][1] -= 1e9f * m0.y;
            sacc[j][2] -= 1e9f * m1.x; sacc[j][3] -= 1e9f * m1.y;
        }

        // ---- online softmax ----
        #pragma unroll
        for (int r = 0; r < 2; r++) {
            float mx = -1e30f;
            #pragma unroll
            for (int j = 0; j < 8; j++)
                mx = fmaxf(mx, fmaxf(sacc[j][2 * r], sacc[j][2 * r + 1]));
            mx = fmaxf(mx, __shfl_xor_sync(0xffffffffu, mx, 1));
            mx = fmaxf(mx, __shfl_xor_sync(0xffffffffu, mx, 2));
            float nm   = fmaxf(rmax[r], mx);
            float corr = __expf(rmax[r] - nm);
            rmax[r] = nm;
            float ps = 0.f;
            #pragma unroll
            for (int j = 0; j < 8; j++) {
                float p0 = __expf(sacc[j][2 * r] - nm);
                float p1 = __expf(sacc[j][2 * r + 1] - nm);
                sacc[j][2 * r] = p0; sacc[j][2 * r + 1] = p1;
                ps += p0 + p1;
            }
            ps += __shfl_xor_sync(0xffffffffu, ps, 1);
            ps += __shfl_xor_sync(0xffffffffu, ps, 2);
            rsum[r] = rsum[r] * corr + ps;
            #pragma unroll
            for (int jn = 0; jn < 8; jn++) {
                oacc[jn][2 * r]     *= corr;
                oacc[jn][2 * r + 1] *= corr;
            }
        }

        // ---- O += (Ph + Pl) @ Vh ----
        #pragma unroll
        for (int kk = 0; kk < 4; kk++) {
            uint32_t ph[4], pl[4];
            split2(sacc[2 * kk][0],     sacc[2 * kk][1],     ph[0], pl[0]);
            split2(sacc[2 * kk][2],     sacc[2 * kk][3],     ph[1], pl[1]);
            split2(sacc[2 * kk + 1][0], sacc[2 * kk + 1][1], ph[2], pl[2]);
            split2(sacc[2 * kk + 1][2], sacc[2 * kk + 1][3], ph[3], pl[3]);
            #pragma unroll
            for (int jd = 0; jd < 4; jd++) {
                uint32_t vh4[4];
                uint32_t off = ((kk * 16 + ((sub & 1) << 3) + l7) * ASKP
                                + jd * 16 + ((sub >> 1) << 3)) * 2;
                ldm_x4_t(vh4, bVh2 + off);
                float* o0 = oacc[2 * jd];
                float* o1 = oacc[2 * jd + 1];
                mma16816(o0, ph, vh4);
                mma16816(o1, ph, vh4 + 2);
                mma16816(o0, pl, vh4);
                mma16816(o1, pl, vh4 + 2);
            }
        }
        __syncthreads();
    }

    // ---- epilogue: normalize, write fp16 hi/lo ----
    const float inv0 = 1.0f / rsum[0];
    const float inv1 = 1.0f / rsum[1];
    const int orow = q0 + wid * 16 + g;
    __half* Ohb = g_Oh + base + (size_t)orow * DM;
    __half* Olb = g_Ol + base + (size_t)orow * DM;
    #pragma unroll
    for (int jn = 0; jn < 8; jn++) {
        int cc = jn * 8 + c2;
        uint32_t hi, lo;
        split2(oacc[jn][0] * inv0, oacc[jn][1] * inv0, hi, lo);
        *(uint32_t*)(Ohb + cc) = hi;
        *(uint32_t*)(Olb + cc) = lo;
        split2(oacc[jn][2] * inv1, oacc[jn][3] * inv1, hi, lo);
        *(uint32_t*)(Ohb + 8 * DM + cc) = hi;
        *(uint32_t*)(Olb + 8 * DM + cc) = lo;
    }
}

// ---------------------------------------------------------------------------
extern "C" void kernel_launch(void* const* d_in, const int* in_sizes, int n_in,
                              void* d_out, int out_size)
{
    (void)in_sizes; (void)n_in; (void)out_size;
    const float* q    = (const float*)d_in[0];
    const float* k    = (const float*)d_in[1];
    const float* v    = (const float*)d_in[2];
    const float* mask = (const float*)d_in[3];
    const float* wq_w = (const float*)d_in[4];
    const float* wq_b = (const float*)d_in[5];
    const float* wk_w = (const float*)d_in[6];
    const float* wk_b = (const float*)d_in[7];
    const float* wv_w = (const float*)d_in[8];
    const float* wv_b = (const float*)d_in[9];
    const float* pl_w = (const float*)d_in[10];
    const float* pl_b = (const float*)d_in[11];
    float* out = (float*)d_out;

    __half *Qh, *Ql, *Kh, *Kl, *Vh, *Vl, *Oh, *Ol, *xhi, *xlo, *whi, *wlo;
    cudaGetSymbolAddress((void**)&Qh, g_Qh);
    cudaGetSymbolAddress((void**)&Ql, g_Ql);
    cudaGetSymbolAddress((void**)&Kh, g_Kh);
    cudaGetSymbolAddress((void**)&Kl, g_Kl);
    cudaGetSymbolAddress((void**)&Vh, g_Vh);
    cudaGetSymbolAddress((void**)&Vl, g_Vl);
    cudaGetSymbolAddress((void**)&Oh, g_Oh);
    cudaGetSymbolAddress((void**)&Ol, g_Ol);
    cudaGetSymbolAddress((void**)&xhi, g_xhi);
    cudaGetSymbolAddress((void**)&xlo, g_xlo);
    cudaGetSymbolAddress((void**)&whi, g_whi);
    cudaGetSymbolAddress((void**)&wlo, g_wlo);

    cudaFuncSetAttribute(gemm_hmma, cudaFuncAttributeMaxDynamicSharedMemorySize,
                         GEMM_SMEM);
    cudaFuncSetAttribute(attn_mma, cudaFuncAttributeMaxDynamicSharedMemorySize,
                         ATTN_SMEM);

    const int NX = MROWS * DM;
    const int NW = DM * DM;
    dim3 gg(DM / BN, MROWS / BM);   // (8, 32)

    split_f16<<<NX / 1024, 256>>>(q, xhi, xlo, NX);
    split_f16<<<NW / 1024, 256>>>(wq_w, whi, wlo, NW);
    gemm_hmma<<<gg, 256, GEMM_SMEM>>>(xhi, xlo, whi, wlo, wq_b,
                                      nullptr, Qh, Ql, 0.125f);
    split_f16<<<NX / 1024, 256>>>(k, xhi, xlo, NX);
    split_f16<<<NW / 1024, 256>>>(wk_w, whi, wlo, NW);
    gemm_hmma<<<gg, 256, GEMM_SMEM>>>(xhi, xlo, whi, wlo, wk_b,
                                      nullptr, Kh, Kl, 1.0f);
    split_f16<<<NX / 1024, 256>>>(v, xhi, xlo, NX);
    split_f16<<<NW / 1024, 256>>>(wv_w, whi, wlo, NW);
    gemm_hmma<<<gg, 256, GEMM_SMEM>>>(xhi, xlo, whi, wlo, wv_b,
                                      nullptr, Vh, Vl, 1.0f);

    attn_mma<<<dim3(SEQ / 128, BATCH * NHEAD), 256, ATTN_SMEM>>>(mask);

    split_f16<<<NW / 1024, 256>>>(pl_w, whi, wlo, NW);
    gemm_hmma<<<gg, 256, GEMM_SMEM>>>(Oh, Ol, whi, wlo, pl_b,
                                      out, nullptr, nullptr, 1.0f);
}

// round 10
// speedup vs baseline: 3.5874x; 1.2535x over previous
#include <cuda_runtime.h>
#include <cuda_fp16.h>
#include <cstdint>

#define BATCH  4
#define SEQ    1024
#define DM     1024
#define NHEAD  16
#define DEPTH  64
#define MROWS  (BATCH * SEQ)

// ---------------- scratch (device globals; allocation-free rule) ------------
__device__ __half g_Qh[(size_t)MROWS * DM];
__device__ __half g_Ql[(size_t)MROWS * DM];
__device__ __half g_Kh[(size_t)MROWS * DM];
__device__ __half g_Vh[(size_t)MROWS * DM];
__device__ __half g_Oh[(size_t)MROWS * DM];
__device__ __half g_xhi[(size_t)MROWS * DM];
__device__ __half g_whi[(size_t)DM * DM];
__device__ __half g_wlo[(size_t)DM * DM];

// ---------------- helpers ----------------------------------------------------
__device__ __forceinline__ uint32_t smem_u32(const void* p) {
    uint32_t a;
    asm("{ .reg .u64 t; cvta.to.shared.u64 t, %1; cvt.u32.u64 %0, t; }"
        : "=r"(a) : "l"(p));
    return a;
}
__device__ __forceinline__ void ldm_x4(uint32_t* r, uint32_t addr) {
    asm volatile("ldmatrix.sync.aligned.m8n8.x4.shared.b16 {%0,%1,%2,%3}, [%4];"
                 : "=r"(r[0]), "=r"(r[1]), "=r"(r[2]), "=r"(r[3]) : "r"(addr));
}
__device__ __forceinline__ void ldm_x4_t(uint32_t* r, uint32_t addr) {
    asm volatile("ldmatrix.sync.aligned.m8n8.x4.trans.shared.b16 {%0,%1,%2,%3}, [%4];"
                 : "=r"(r[0]), "=r"(r[1]), "=r"(r[2]), "=r"(r[3]) : "r"(addr));
}
__device__ __forceinline__ void mma16816(float* d, const uint32_t* a,
                                         const uint32_t* b) {
    asm("mma.sync.aligned.m16n8k16.row.col.f32.f16.f16.f32 "
        "{%0,%1,%2,%3}, {%4,%5,%6,%7}, {%8,%9}, {%0,%1,%2,%3};"
        : "+f"(d[0]), "+f"(d[1]), "+f"(d[2]), "+f"(d[3])
        : "r"(a[0]), "r"(a[1]), "r"(a[2]), "r"(a[3]), "r"(b[0]), "r"(b[1]));
}
__device__ __forceinline__ void split2(float a, float b, uint32_t& hi,
                                       uint32_t& lo) {
    __half ha = __float2half_rn(a), hb = __float2half_rn(b);
    __half la = __float2half_rn(a - __half2float(ha));
    __half lb = __float2half_rn(b - __half2float(hb));
    hi = (uint32_t)__half_as_ushort(ha) | ((uint32_t)__half_as_ushort(hb) << 16);
    lo = (uint32_t)__half_as_ushort(la) | ((uint32_t)__half_as_ushort(lb) << 16);
}
#define CP_ASYNC16(saddr, gptr) \
    asm volatile("cp.async.cg.shared.global [%0], [%1], 16;" \
                 :: "r"(saddr), "l"(gptr))
#define CP_COMMIT() asm volatile("cp.async.commit_group;")
#define CP_WAIT1()  asm volatile("cp.async.wait_group 1;")
#define CP_WAIT0()  asm volatile("cp.async.wait_group 0;")

// ---------------- fp32 -> fp16 conversions -----------------------------------
__global__ __launch_bounds__(256)
void conv_f16(const float* __restrict__ x, __half* __restrict__ hi, int n)
{
    int i = (blockIdx.x * 256 + threadIdx.x) * 4;
    if (i >= n) return;
    float4 v = *(const float4*)(x + i);
    __half h2[4] = {__float2half_rn(v.x), __float2half_rn(v.y),
                    __float2half_rn(v.z), __float2half_rn(v.w)};
    *(uint2*)(hi + i) = *(uint2*)h2;
}

__global__ __launch_bounds__(256)
void split_f16(const float* __restrict__ x, __half* __restrict__ hi,
               __half* __restrict__ lo, int n)
{
    int i = (blockIdx.x * 256 + threadIdx.x) * 4;
    if (i >= n) return;
    float4 v = *(const float4*)(x + i);
    float a[4] = {v.x, v.y, v.z, v.w};
    __half h2[4], l2[4];
    #pragma unroll
    for (int j = 0; j < 4; j++) {
        __half h = __float2half_rn(a[j]);
        h2[j] = h;
        l2[j] = __float2half_rn(a[j] - __half2float(h));
    }
    *(uint2*)(hi + i) = *(uint2*)h2;
    *(uint2*)(lo + i) = *(uint2*)l2;
}

// ---------------- 2-pass HMMA GEMM: C = (A@(Whi+Wlo)^T + bias)*scale --------
// A is fp16-rounded activation (single tile); W kept as hi/lo split.
#define BM 128
#define BN 128
#define BKG 32
#define SKPG 40
#define GT_H (128 * SKPG)            // 5120 halves per tile
#define GSTAGE_H (3 * GT_H)          // A, Wh, Wl
#define GEMM_SMEM (2 * GSTAGE_H * 2) // 61440 bytes

__device__ __forceinline__ void gemm_issue(uint32_t sb, int buf, int k0,
    const __half* A0, const __half* W0, const __half* W1, int t)
{
    const __half* bases[3] = {A0, W0, W1};
    const uint32_t stb = sb + buf * (GSTAGE_H * 2);
    #pragma unroll
    for (int j = 0; j < 6; j++) {
        const int tile = j >> 1;
        const int r = t + (j & 1) * 256;   // 0..511
        const int row = r >> 2, c16 = r & 3;
        const __half* gp = bases[tile] + (size_t)row * DM + k0 + c16 * 8;
        uint32_t sa = stb + (tile * GT_H + row * SKPG + c16 * 8) * 2;
        CP_ASYNC16(sa, gp);
    }
    CP_COMMIT();
}

__global__ void __launch_bounds__(256, 2)
gemm_hmma(const __half* __restrict__ Ahi,
          const __half* __restrict__ Whi, const __half* __restrict__ Wlo,
          const float* __restrict__ bias,
          float* __restrict__ Cf, __half* __restrict__ Chi,
          __half* __restrict__ Clo, float scale)
{
    extern __shared__ __half sh[];
    const uint32_t sb = smem_u32(sh);

    const int t      = threadIdx.x;
    const int lane   = t & 31;
    const int wid    = t >> 5;
    const int warp_m = wid & 3;
    const int warp_n = wid >> 2;
    const int sub    = lane >> 3;
    const int l7     = lane & 7;
    const int bm     = blockIdx.y * BM;
    const int bn     = blockIdx.x * BN;

    const __half* A0 = Ahi + (size_t)bm * DM;
    const __half* W0 = Whi + (size_t)bn * DM;
    const __half* W1 = Wlo + (size_t)bn * DM;

    float acc[2][8][4];
    #pragma unroll
    for (int i = 0; i < 2; i++)
        #pragma unroll
        for (int j = 0; j < 8; j++)
            #pragma unroll
            for (int c = 0; c < 4; c++) acc[i][j][c] = 0.f;

    const uint32_t a_off =
        ((warp_m * 32 + (l7 | ((sub & 1) << 3))) * SKPG + ((sub >> 1) << 3)) * 2;
    const uint32_t b_off =
        ((warp_n * 64 + (l7 + ((sub >> 1) << 3))) * SKPG + ((sub & 1) << 3)) * 2;

    gemm_issue(sb, 0, 0, A0, W0, W1, t);

    const int NS = DM / BKG;   // 32
    for (int kc = 0; kc < NS; kc++) {
        const int buf = kc & 1;
        if (kc + 1 < NS) {
            gemm_issue(sb, buf ^ 1, (kc + 1) * BKG, A0, W0, W1, t);
            CP_WAIT1();
        } else {
            CP_WAIT0();
        }
        __syncthreads();

        const uint32_t bA  = sb + buf * (GSTAGE_H * 2);
        const uint32_t bW  = bA + GT_H * 2;
        const uint32_t bWl = bA + 2 * GT_H * 2;

        #pragma unroll
        for (int k16 = 0; k16 < 2; k16++) {
            const uint32_t ko = k16 * 32;
            uint32_t ah[2][4];
            #pragma unroll
            for (int im = 0; im < 2; im++)
                ldm_x4(ah[im], bA + a_off + im * (16 * SKPG * 2) + ko);
            #pragma unroll
            for (int jn16 = 0; jn16 < 4; jn16++) {
                uint32_t off = b_off + jn16 * (16 * SKPG * 2) + ko;
                uint32_t rh[4], rl[4];
                ldm_x4(rh, bW + off);
                ldm_x4(rl, bWl + off);
                float* a00 = acc[0][jn16 * 2];
                float* a10 = acc[1][jn16 * 2];
                float* a01 = acc[0][jn16 * 2 + 1];
                float* a11 = acc[1][jn16 * 2 + 1];
                mma16816(a00, ah[0], rh);
                mma16816(a10, ah[1], rh);
                mma16816(a01, ah[0], rh + 2);
                mma16816(a11, ah[1], rh + 2);
                mma16816(a00, ah[0], rl);
                mma16816(a10, ah[1], rl);
                mma16816(a01, ah[0], rl + 2);
                mma16816(a11, ah[1], rl + 2);
            }
        }
        __syncthreads();
    }

    const int g  = lane >> 2;
    const int tc = (lane & 3) * 2;
    #pragma unroll
    for (int im = 0; im < 2; im++) {
        const int r0 = bm + warp_m * 32 + im * 16 + g;
        #pragma unroll
        for (int jn = 0; jn < 8; jn++) {
            const int c = bn + warp_n * 64 + jn * 8 + tc;
            const float b0 = bias[c], b1 = bias[c + 1];
            float v0 = (acc[im][jn][0] + b0) * scale;
            float v1 = (acc[im][jn][1] + b1) * scale;
            float v2 = (acc[im][jn][2] + b0) * scale;
            float v3 = (acc[im][jn][3] + b1) * scale;
            if (Cf) {
                *(float2*)(Cf + (size_t)r0 * DM + c) = make_float2(v0, v1);
                *(float2*)(Cf + (size_t)(r0 + 8) * DM + c) = make_float2(v2, v3);
            } else {
                uint32_t hi, lo;
                split2(v0, v1, hi, lo);
                *(uint32_t*)(Chi + (size_t)r0 * DM + c) = hi;
                if (Clo) *(uint32_t*)(Clo + (size_t)r0 * DM + c) = lo;
                split2(v2, v3, hi, lo);
                *(uint32_t*)(Chi + (size_t)(r0 + 8) * DM + c) = hi;
                if (Clo) *(uint32_t*)(Clo + (size_t)(r0 + 8) * DM + c) = lo;
            }
        }
    }
}

// ---------------- HMMA flash attention, slim 2-pass variant ------------------
//   S = Qh*Kh + Ql*Kh   (K fp16-rounded)
//   O = Ph*Vh + Pl*Vh   (V fp16-rounded)
#define ATK  64
#define ASKP 72
#define AT_H (64 * ASKP)
#define ASTAGE_H (2 * AT_H)
#define ATTN_SMEM (2 * ASTAGE_H * 2)   // 36864 bytes

__device__ __forceinline__ void attn_issue(uint32_t sb, int buf, int k0,
    const __half* Khb, const __half* Vhb, int t)
{
    const uint32_t stb = sb + buf * (ASTAGE_H * 2);
    #pragma unroll
    for (int j = 0; j < 4; j++) {
        const int tile = j >> 1;           // 0=Kh, 1=Vh
        const int r = t + (j & 1) * 256;
        const int row = r >> 3, c16 = r & 7;
        const __half* gp = (tile ? Vhb : Khb) + (size_t)(k0 + row) * DM
                           + c16 * 8;
        uint32_t sa = stb + (tile * AT_H + row * ASKP + c16 * 8) * 2;
        CP_ASYNC16(sa, gp);
    }
    CP_COMMIT();
}

__global__ void __launch_bounds__(256, 2)
attn_mma(const float* __restrict__ mask)
{
    extern __shared__ __half sh[];
    const uint32_t sb = smem_u32(sh);

    const int t    = threadIdx.x;
    const int lane = t & 31;
    const int wid  = t >> 5;
    const int sub  = lane >> 3;
    const int l7   = lane & 7;
    const int g    = lane >> 2;
    const int c2   = (lane & 3) * 2;

    const int q0 = blockIdx.x * 128;
    const int bh = blockIdx.y;
    const int b  = bh >> 4;
    const int h  = bh & 15;

    const size_t base = (size_t)b * SEQ * DM + h * DEPTH;
    const __half* Qhb = g_Qh + base;
    const __half* Qlb = g_Ql + base;
    const __half* Khb = g_Kh + base;
    const __half* Vhb = g_Vh + base;

    // ---- stage Q: hi -> stage0 area, lo -> stage1 area ----
    #pragma unroll
    for (int j = 0; j < 8; j++) {
        const int tensor = j >> 2;
        const int r = t + (j & 3) * 256;
        const int row = r >> 3, c16 = r & 7;
        const __half* src = (tensor ? Qlb : Qhb) + (size_t)(q0 + row) * DM
                            + c16 * 8;
        __half* dst = sh + tensor * ASTAGE_H + (row >> 6) * AT_H
                      + (row & 63) * ASKP + c16 * 8;
        *(uint4*)dst = *(const uint4*)src;
    }
    __syncthreads();

    uint32_t qh[4][4], ql[4][4];
    {
        const int qrow = wid * 16 + (l7 | ((sub & 1) << 3));
        const uint32_t hb = sb + ((qrow >> 6) * AT_H + (qrow & 63) * ASKP) * 2;
        #pragma unroll
        for (int kk = 0; kk < 4; kk++) {
            uint32_t off = (((sub >> 1) << 3) + kk * 16) * 2;
            ldm_x4(qh[kk], hb + off);
            ldm_x4(ql[kk], hb + ASTAGE_H * 2 + off);
        }
    }
    __syncthreads();

    float oacc[8][4];
    #pragma unroll
    for (int j = 0; j < 8; j++)
        #pragma unroll
        for (int c = 0; c < 4; c++) oacc[j][c] = 0.f;
    float rmax[2] = {-1e30f, -1e30f};
    float rsum[2] = {0.f, 0.f};

    const int mrow = q0 + wid * 16 + g;

    attn_issue(sb, 0, 0, Khb, Vhb, t);

    const int NC = SEQ / ATK;   // 16
    for (int kc = 0; kc < NC; kc++) {
        const int buf = kc & 1;
        const int k0 = kc * ATK;
        if (kc + 1 < NC) {
            attn_issue(sb, buf ^ 1, (kc + 1) * ATK, Khb, Vhb, t);
            CP_WAIT1();
        } else {
            CP_WAIT0();
        }
        __syncthreads();

        const uint32_t stb  = sb + buf * (ASTAGE_H * 2);
        const uint32_t bKh2 = stb;
        const uint32_t bVh2 = stb + AT_H * 2;

        float sacc[8][4];
        #pragma unroll
        for (int j = 0; j < 8; j++)
            #pragma unroll
            for (int c = 0; c < 4; c++) sacc[j][c] = 0.f;

        #pragma unroll
        for (int kk = 0; kk < 4; kk++) {
            #pragma unroll
            for (int jp = 0; jp < 4; jp++) {
                uint32_t rh[4];
                uint32_t off = ((jp * 16 + l7 + ((sub >> 1) << 3)) * ASKP
                                + ((sub & 1) << 3) + kk * 16) * 2;
                ldm_x4(rh, bKh2 + off);
                float* s0 = sacc[2 * jp];
                float* s1 = sacc[2 * jp + 1];
                mma16816(s0, qh[kk], rh);
                mma16816(s1, qh[kk], rh + 2);
                mma16816(s0, ql[kk], rh);
                mma16816(s1, ql[kk], rh + 2);
            }
        }

        #pragma unroll
        for (int j = 0; j < 8; j++) {
            int col = k0 + j * 8 + c2;
            float2 m0 = *(const float2*)(mask + (size_t)mrow * SEQ + col);
            float2 m1 = *(const float2*)(mask + (size_t)(mrow + 8) * SEQ + col);
            sacc[j][0] -= 1e9f * m0.x; sacc[j][1] -= 1e9f * m0.y;
            sacc[j][2] -= 1e9f * m1.x; sacc[j][3] -= 1e9f * m1.y;
        }

        #pragma unroll
        for (int r = 0; r < 2; r++) {
            float mx = -1e30f;
            #pragma unroll
            for (int j = 0; j < 8; j++)
                mx = fmaxf(mx, fmaxf(sacc[j][2 * r], sacc[j][2 * r + 1]));
            mx = fmaxf(mx, __shfl_xor_sync(0xffffffffu, mx, 1));
            mx = fmaxf(mx, __shfl_xor_sync(0xffffffffu, mx, 2));
            float nm   = fmaxf(rmax[r], mx);
            float corr = __expf(rmax[r] - nm);
            rmax[r] = nm;
            float ps = 0.f;
            #pragma unroll
            for (int j = 0; j < 8; j++) {
                float p0 = __expf(sacc[j][2 * r] - nm);
                float p1 = __expf(sacc[j][2 * r + 1] - nm);
                sacc[j][2 * r] = p0; sacc[j][2 * r + 1] = p1;
                ps += p0 + p1;
            }
            ps += __shfl_xor_sync(0xffffffffu, ps, 1);
            ps += __shfl_xor_sync(0xffffffffu, ps, 2);
            rsum[r] = rsum[r] * corr + ps;
            #pragma unroll
            for (int jn = 0; jn < 8; jn++) {
                oacc[jn][2 * r]     *= corr;
                oacc[jn][2 * r + 1] *= corr;
            }
        }

        #pragma unroll
        for (int kk = 0; kk < 4; kk++) {
            uint32_t ph[4], pl[4];
            split2(sacc[2 * kk][0],     sacc[2 * kk][1],     ph[0], pl[0]);
            split2(sacc[2 * kk][2],     sacc[2 * kk][3],     ph[1], pl[1]);
            split2(sacc[2 * kk + 1][0], sacc[2 * kk + 1][1], ph[2], pl[2]);
            split2(sacc[2 * kk + 1][2], sacc[2 * kk + 1][3], ph[3], pl[3]);
            #pragma unroll
            for (int jd = 0; jd < 4; jd++) {
                uint32_t vh4[4];
                uint32_t off = ((kk * 16 + ((sub & 1) << 3) + l7) * ASKP
                                + jd * 16 + ((sub >> 1) << 3)) * 2;
                ldm_x4_t(vh4, bVh2 + off);
                float* o0 = oacc[2 * jd];
                float* o1 = oacc[2 * jd + 1];
                mma16816(o0, ph, vh4);
                mma16816(o1, ph, vh4 + 2);
                mma16816(o0, pl, vh4);
                mma16816(o1, pl, vh4 + 2);
            }
        }
        __syncthreads();
    }

    // ---- epilogue: normalize, write fp16 (hi only) ----
    const float inv0 = 1.0f / rsum[0];
    const float inv1 = 1.0f / rsum[1];
    const int orow = q0 + wid * 16 + g;
    __half* Ohb = g_Oh + base + (size_t)orow * DM;
    #pragma unroll
    for (int jn = 0; jn < 8; jn++) {
        int cc = jn * 8 + c2;
        __half2 o01 = __floats2half2_rn(oacc[jn][0] * inv0, oacc[jn][1] * inv0);
        *(__half2*)(Ohb + cc) = o01;
        __half2 o23 = __floats2half2_rn(oacc[jn][2] * inv1, oacc[jn][3] * inv1);
        *(__half2*)(Ohb + 8 * DM + cc) = o23;
    }
}

// ---------------------------------------------------------------------------
extern "C" void kernel_launch(void* const* d_in, const int* in_sizes, int n_in,
                              void* d_out, int out_size)
{
    (void)in_sizes; (void)n_in; (void)out_size;
    const float* q    = (const float*)d_in[0];
    const float* k    = (const float*)d_in[1];
    const float* v    = (const float*)d_in[2];
    const float* mask = (const float*)d_in[3];
    const float* wq_w = (const float*)d_in[4];
    const float* wq_b = (const float*)d_in[5];
    const float* wk_w = (const float*)d_in[6];
    const float* wk_b = (const float*)d_in[7];
    const float* wv_w = (const float*)d_in[8];
    const float* wv_b = (const float*)d_in[9];
    const float* pl_w = (const float*)d_in[10];
    const float* pl_b = (const float*)d_in[11];
    float* out = (float*)d_out;

    __half *Qh, *Ql, *Kh, *Vh, *Oh, *xhi, *whi, *wlo;
    cudaGetSymbolAddress((void**)&Qh, g_Qh);
    cudaGetSymbolAddress((void**)&Ql, g_Ql);
    cudaGetSymbolAddress((void**)&Kh, g_Kh);
    cudaGetSymbolAddress((void**)&Vh, g_Vh);
    cudaGetSymbolAddress((void**)&Oh, g_Oh);
    cudaGetSymbolAddress((void**)&xhi, g_xhi);
    cudaGetSymbolAddress((void**)&whi, g_whi);
    cudaGetSymbolAddress((void**)&wlo, g_wlo);

    cudaFuncSetAttribute(gemm_hmma, cudaFuncAttributeMaxDynamicSharedMemorySize,
                         GEMM_SMEM);
    cudaFuncSetAttribute(attn_mma, cudaFuncAttributeMaxDynamicSharedMemorySize,
                         ATTN_SMEM);

    const int NX = MROWS * DM;
    const int NW = DM * DM;
    dim3 gg(DM / BN, MROWS / BM);   // (8, 32)

    // Q projection (1/sqrt(64) folded in): Q needs hi+lo
    conv_f16<<<NX / 1024, 256>>>(q, xhi, NX);
    split_f16<<<NW / 1024, 256>>>(wq_w, whi, wlo, NW);
    gemm_hmma<<<gg, 256, GEMM_SMEM>>>(xhi, whi, wlo, wq_b,
                                      nullptr, Qh, Ql, 0.125f);
    // K projection: attention reads Kh only
    conv_f16<<<NX / 1024, 256>>>(k, xhi, NX);
    split_f16<<<NW / 1024, 256>>>(wk_w, whi, wlo, NW);
    gemm_hmma<<<gg, 256, GEMM_SMEM>>>(xhi, whi, wlo, wk_b,
                                      nullptr, Kh, nullptr, 1.0f);
    // V projection: attention reads Vh only
    conv_f16<<<NX / 1024, 256>>>(v, xhi, NX);
    split_f16<<<NW / 1024, 256>>>(wv_w, whi, wlo, NW);
    gemm_hmma<<<gg, 256, GEMM_SMEM>>>(xhi, whi, wlo, wv_b,
                                      nullptr, Vh, nullptr, 1.0f);

    // attention (writes Oh only)
    attn_mma<<<dim3(SEQ / 128, BATCH * NHEAD), 256, ATTN_SMEM>>>(mask);

    // output projection (activation = Oh, fp32 out)
    split_f16<<<NW / 1024, 256>>>(pl_w, whi, wlo, NW);
    gemm_hmma<<<gg, 256, GEMM_SMEM>>>(Oh, whi, wlo, pl_b,
                                      out, nullptr, nullptr, 1.0f);
}

// round 12
// speedup vs baseline: 5.2504x; 1.4635x over previous
#include <cuda_runtime.h>
#include <cuda_fp16.h>
#include <cstdint>

#define BATCH  4
#define SEQ    1024
#define DM     1024
#define NHEAD  16
#define DEPTH  64
#define MROWS  (BATCH * SEQ)

// ---------------- scratch (device globals; allocation-free rule) ------------
__device__ __half g_Qh[(size_t)MROWS * DM];
__device__ __half g_Kh[(size_t)MROWS * DM];
__device__ __half g_Vh[(size_t)MROWS * DM];
__device__ __half g_Oh[(size_t)MROWS * DM];
__device__ __half g_xhi[(size_t)MROWS * DM];
__device__ __half g_whi[(size_t)DM * DM];

// ---------------- helpers ----------------------------------------------------
__device__ __forceinline__ uint32_t smem_u32(const void* p) {
    uint32_t a;
    asm("{ .reg .u64 t; cvta.to.shared.u64 t, %1; cvt.u32.u64 %0, t; }"
        : "=r"(a) : "l"(p));
    return a;
}
__device__ __forceinline__ void ldm_x4(uint32_t* r, uint32_t addr) {
    asm volatile("ldmatrix.sync.aligned.m8n8.x4.shared.b16 {%0,%1,%2,%3}, [%4];"
                 : "=r"(r[0]), "=r"(r[1]), "=r"(r[2]), "=r"(r[3]) : "r"(addr));
}
__device__ __forceinline__ void ldm_x4_t(uint32_t* r, uint32_t addr) {
    asm volatile("ldmatrix.sync.aligned.m8n8.x4.trans.shared.b16 {%0,%1,%2,%3}, [%4];"
                 : "=r"(r[0]), "=r"(r[1]), "=r"(r[2]), "=r"(r[3]) : "r"(addr));
}
__device__ __forceinline__ void mma16816(float* d, const uint32_t* a,
                                         const uint32_t* b) {
    asm("mma.sync.aligned.m16n8k16.row.col.f32.f16.f16.f32 "
        "{%0,%1,%2,%3}, {%4,%5,%6,%7}, {%8,%9}, {%0,%1,%2,%3};"
        : "+f"(d[0]), "+f"(d[1]), "+f"(d[2]), "+f"(d[3])
        : "r"(a[0]), "r"(a[1]), "r"(a[2]), "r"(a[3]), "r"(b[0]), "r"(b[1]));
}
__device__ __forceinline__ uint32_t packh2(float a, float b) {
    __half2 h = __floats2half2_rn(a, b);
    return *(uint32_t*)&h;
}
#define CP_ASYNC16(saddr, gptr) \
    asm volatile("cp.async.cg.shared.global [%0], [%1], 16;" \
                 :: "r"(saddr), "l"(gptr))
#define CP_COMMIT() asm volatile("cp.async.commit_group;")
#define CP_WAIT1()  asm volatile("cp.async.wait_group 1;")
#define CP_WAIT0()  asm volatile("cp.async.wait_group 0;")

// ---------------- fp32 -> fp16 conversion (8 elems/thread) -------------------
__global__ __launch_bounds__(256)
void conv_f16(const float* __restrict__ x, __half* __restrict__ hi, int n)
{
    int i = (blockIdx.x * 256 + threadIdx.x) * 8;
    if (i >= n) return;
    float4 v0 = *(const float4*)(x + i);
    float4 v1 = *(const float4*)(x + i + 4);
    __half h[8] = {__float2half_rn(v0.x), __float2half_rn(v0.y),
                   __float2half_rn(v0.z), __float2half_rn(v0.w),
                   __float2half_rn(v1.x), __float2half_rn(v1.y),
                   __float2half_rn(v1.z), __float2half_rn(v1.w)};
    *(uint4*)(hi + i) = *(uint4*)h;
}

// ---------------- 1-pass HMMA GEMM: C = (A@W^T + bias)*scale ----------------
#define BM 128
#define BN 128
#define BKG 32
#define SKPG 40
#define GT_H (128 * SKPG)            // 5120 halves per tile
#define GSTAGE_H (2 * GT_H)          // A, W
#define GEMM_SMEM (2 * GSTAGE_H * 2) // 40960 bytes

__device__ __forceinline__ void gemm_issue(uint32_t sb, int buf, int k0,
    const __half* A0, const __half* W0, int t)
{
    const __half* bases[2] = {A0, W0};
    const uint32_t stb = sb + buf * (GSTAGE_H * 2);
    #pragma unroll
    for (int j = 0; j < 4; j++) {
        const int tile = j >> 1;
        const int r = t + (j & 1) * 256;   // 0..511
        const int row = r >> 2, c16 = r & 3;
        const __half* gp = bases[tile] + (size_t)row * DM + k0 + c16 * 8;
        uint32_t sa = stb + (tile * GT_H + row * SKPG + c16 * 8) * 2;
        CP_ASYNC16(sa, gp);
    }
    CP_COMMIT();
}

__global__ void __launch_bounds__(256, 2)
gemm_hmma(const __half* __restrict__ Ahi, const __half* __restrict__ Whi,
          const float* __restrict__ bias,
          float* __restrict__ Cf, __half* __restrict__ Chi, float scale)
{
    extern __shared__ __half sh[];
    const uint32_t sb = smem_u32(sh);

    const int t      = threadIdx.x;
    const int lane   = t & 31;
    const int wid    = t >> 5;
    const int warp_m = wid & 3;
    const int warp_n = wid >> 2;
    const int sub    = lane >> 3;
    const int l7     = lane & 7;
    const int bm     = blockIdx.y * BM;
    const int bn     = blockIdx.x * BN;

    const __half* A0 = Ahi + (size_t)bm * DM;
    const __half* W0 = Whi + (size_t)bn * DM;

    float acc[2][8][4];
    #pragma unroll
    for (int i = 0; i < 2; i++)
        #pragma unroll
        for (int j = 0; j < 8; j++)
            #pragma unroll
            for (int c = 0; c < 4; c++) acc[i][j][c] = 0.f;

    const uint32_t a_off =
        ((warp_m * 32 + (l7 | ((sub & 1) << 3))) * SKPG + ((sub >> 1) << 3)) * 2;
    const uint32_t b_off =
        ((warp_n * 64 + (l7 + ((sub >> 1) << 3))) * SKPG + ((sub & 1) << 3)) * 2;

    gemm_issue(sb, 0, 0, A0, W0, t);

    const int NS = DM / BKG;   // 32
    for (int kc = 0; kc < NS; kc++) {
        const int buf = kc & 1;
        if (kc + 1 < NS) {
            gemm_issue(sb, buf ^ 1, (kc + 1) * BKG, A0, W0, t);
            CP_WAIT1();
        } else {
            CP_WAIT0();
        }
        __syncthreads();

        const uint32_t bA = sb + buf * (GSTAGE_H * 2);
        const uint32_t bW = bA + GT_H * 2;

        #pragma unroll
        for (int k16 = 0; k16 < 2; k16++) {
            const uint32_t ko = k16 * 32;
            uint32_t ah[2][4];
            #pragma unroll
            for (int im = 0; im < 2; im++)
                ldm_x4(ah[im], bA + a_off + im * (16 * SKPG * 2) + ko);
            #pragma unroll
            for (int jn16 = 0; jn16 < 4; jn16++) {
                uint32_t rh[4];
                ldm_x4(rh, bW + b_off + jn16 * (16 * SKPG * 2) + ko);
                mma16816(acc[0][jn16 * 2],     ah[0], rh);
                mma16816(acc[1][jn16 * 2],     ah[1], rh);
                mma16816(acc[0][jn16 * 2 + 1], ah[0], rh + 2);
                mma16816(acc[1][jn16 * 2 + 1], ah[1], rh + 2);
            }
        }
        __syncthreads();
    }

    const int g  = lane >> 2;
    const int tc = (lane & 3) * 2;
    #pragma unroll
    for (int im = 0; im < 2; im++) {
        const int r0 = bm + warp_m * 32 + im * 16 + g;
        #pragma unroll
        for (int jn = 0; jn < 8; jn++) {
            const int c = bn + warp_n * 64 + jn * 8 + tc;
            const float b0 = bias[c], b1 = bias[c + 1];
            float v0 = (acc[im][jn][0] + b0) * scale;
            float v1 = (acc[im][jn][1] + b1) * scale;
            float v2 = (acc[im][jn][2] + b0) * scale;
            float v3 = (acc[im][jn][3] + b1) * scale;
            if (Cf) {
                *(float2*)(Cf + (size_t)r0 * DM + c) = make_float2(v0, v1);
                *(float2*)(Cf + (size_t)(r0 + 8) * DM + c) = make_float2(v2, v3);
            } else {
                *(uint32_t*)(Chi + (size_t)r0 * DM + c) = packh2(v0, v1);
                *(uint32_t*)(Chi + (size_t)(r0 + 8) * DM + c) = packh2(v2, v3);
            }
        }
    }
}

// ---------------- HMMA flash attention, 1-pass fp16 --------------------------
//   S = Qh*Kh ; O = Ph*Vh   (all operands fp16-rounded, fp32 accum)
#define ATK  64
#define ASKP 72
#define AT_H (64 * ASKP)
#define ASTAGE_H (2 * AT_H)
#define ATTN_SMEM (2 * ASTAGE_H * 2)   // 36864 bytes

__device__ __forceinline__ void attn_issue(uint32_t sb, int buf, int k0,
    const __half* Khb, const __half* Vhb, int t)
{
    const uint32_t stb = sb + buf * (ASTAGE_H * 2);
    #pragma unroll
    for (int j = 0; j < 4; j++) {
        const int tile = j >> 1;           // 0=Kh, 1=Vh
        const int r = t + (j & 1) * 256;
        const int row = r >> 3, c16 = r & 7;
        const __half* gp = (tile ? Vhb : Khb) + (size_t)(k0 + row) * DM
                           + c16 * 8;
        uint32_t sa = stb + (tile * AT_H + row * ASKP + c16 * 8) * 2;
        CP_ASYNC16(sa, gp);
    }
    CP_COMMIT();
}

__global__ void __launch_bounds__(256, 2)
attn_mma(const float* __restrict__ mask)
{
    extern __shared__ __half sh[];
    const uint32_t sb = smem_u32(sh);

    const int t    = threadIdx.x;
    const int lane = t & 31;
    const int wid  = t >> 5;
    const int sub  = lane >> 3;
    const int l7   = lane & 7;
    const int g    = lane >> 2;
    const int c2   = (lane & 3) * 2;

    const int q0 = blockIdx.x * 128;
    const int bh = blockIdx.y;
    const int b  = bh >> 4;
    const int h  = bh & 15;

    const size_t base = (size_t)b * SEQ * DM + h * DEPTH;
    const __half* Qhb = g_Qh + base;
    const __half* Khb = g_Kh + base;
    const __half* Vhb = g_Vh + base;

    // ---- stage Q tile (128 rows x 64) across both stage areas ----
    #pragma unroll
    for (int j = 0; j < 4; j++) {
        const int r = t + j * 256;            // 0..1023
        const int row = r >> 3, c16 = r & 7;
        const __half* src = Qhb + (size_t)(q0 + row) * DM + c16 * 8;
        __half* dst = sh + (row >> 6) * AT_H + (row & 63) * ASKP + c16 * 8;
        *(uint4*)dst = *(const uint4*)src;
    }
    __syncthreads();

    uint32_t qh[4][4];
    {
        const int qrow = wid * 16 + (l7 | ((sub & 1) << 3));
        const uint32_t hb = sb + ((qrow >> 6) * AT_H + (qrow & 63) * ASKP) * 2;
        #pragma unroll
        for (int kk = 0; kk < 4; kk++)
            ldm_x4(qh[kk], hb + (((sub >> 1) << 3) + kk * 16) * 2);
    }
    __syncthreads();

    float oacc[8][4];
    #pragma unroll
    for (int j = 0; j < 8; j++)
        #pragma unroll
        for (int c = 0; c < 4; c++) oacc[j][c] = 0.f;
    float rmax[2] = {-1e30f, -1e30f};
    float rsum[2] = {0.f, 0.f};

    const int mrow = q0 + wid * 16 + g;

    attn_issue(sb, 0, 0, Khb, Vhb, t);

    const int NC = SEQ / ATK;   // 16
    for (int kc = 0; kc < NC; kc++) {
        const int buf = kc & 1;
        const int k0 = kc * ATK;
        if (kc + 1 < NC) {
            attn_issue(sb, buf ^ 1, (kc + 1) * ATK, Khb, Vhb, t);
            CP_WAIT1();
        } else {
            CP_WAIT0();
        }
        __syncthreads();

        const uint32_t stb  = sb + buf * (ASTAGE_H * 2);
        const uint32_t bKh2 = stb;
        const uint32_t bVh2 = stb + AT_H * 2;

        // ---- S = Qh K^T ----
        float sacc[8][4];
        #pragma unroll
        for (int j = 0; j < 8; j++)
            #pragma unroll
            for (int c = 0; c < 4; c++) sacc[j][c] = 0.f;

        #pragma unroll
        for (int kk = 0; kk < 4; kk++) {
            #pragma unroll
            for (int jp = 0; jp < 4; jp++) {
                uint32_t rh[4];
                uint32_t off = ((jp * 16 + l7 + ((sub >> 1) << 3)) * ASKP
                                + ((sub & 1) << 3) + kk * 16) * 2;
                ldm_x4(rh, bKh2 + off);
                mma16816(sacc[2 * jp],     qh[kk], rh);
                mma16816(sacc[2 * jp + 1], qh[kk], rh + 2);
            }
        }

        // ---- mask ----
        #pragma unroll
        for (int j = 0; j < 8; j++) {
            int col = k0 + j * 8 + c2;
            float2 m0 = *(const float2*)(mask + (size_t)mrow * SEQ + col);
            float2 m1 = *(const float2*)(mask + (size_t)(mrow + 8) * SEQ + col);
            sacc[j][0] -= 1e9f * m0.x; sacc[j][1] -= 1e9f * m0.y;
            sacc[j][2] -= 1e9f * m1.x; sacc[j][3] -= 1e9f * m1.y;
        }

        // ---- online softmax ----
        #pragma unroll
        for (int r = 0; r < 2; r++) {
            float mx = -1e30f;
            #pragma unroll
            for (int j = 0; j < 8; j++)
                mx = fmaxf(mx, fmaxf(sacc[j][2 * r], sacc[j][2 * r + 1]));
            mx = fmaxf(mx, __shfl_xor_sync(0xffffffffu, mx, 1));
            mx = fmaxf(mx, __shfl_xor_sync(0xffffffffu, mx, 2));
            float nm   = fmaxf(rmax[r], mx);
            float corr = __expf(rmax[r] - nm);
            rmax[r] = nm;
            float ps = 0.f;
            #pragma unroll
            for (int j = 0; j < 8; j++) {
                float p0 = __expf(sacc[j][2 * r] - nm);
                float p1 = __expf(sacc[j][2 * r + 1] - nm);
                sacc[j][2 * r] = p0; sacc[j][2 * r + 1] = p1;
                ps += p0 + p1;
            }
            ps += __shfl_xor_sync(0xffffffffu, ps, 1);
            ps += __shfl_xor_sync(0xffffffffu, ps, 2);
            rsum[r] = rsum[r] * corr + ps;
            #pragma unroll
            for (int jn = 0; jn < 8; jn++) {
                oacc[jn][2 * r]     *= corr;
                oacc[jn][2 * r + 1] *= corr;
            }
        }

        // ---- O += P @ Vh (P fp16 1-pass) ----
        #pragma unroll
        for (int kk = 0; kk < 4; kk++) {
            uint32_t ph[4];
            ph[0] = packh2(sacc[2 * kk][0],     sacc[2 * kk][1]);
            ph[1] = packh2(sacc[2 * kk][2],     sacc[2 * kk][3]);
            ph[2] = packh2(sacc[2 * kk + 1][0], sacc[2 * kk + 1][1]);
            ph[3] = packh2(sacc[2 * kk + 1][2], sacc[2 * kk + 1][3]);
            #pragma unroll
            for (int jd = 0; jd < 4; jd++) {
                uint32_t vh4[4];
                uint32_t off = ((kk * 16 + ((sub & 1) << 3) + l7) * ASKP
                                + jd * 16 + ((sub >> 1) << 3)) * 2;
                ldm_x4_t(vh4, bVh2 + off);
                mma16816(oacc[2 * jd],     ph, vh4);
                mma16816(oacc[2 * jd + 1], ph, vh4 + 2);
            }
        }
        __syncthreads();
    }

    // ---- epilogue: normalize, write fp16 ----
    const float inv0 = 1.0f / rsum[0];
    const float inv1 = 1.0f / rsum[1];
    const int orow = q0 + wid * 16 + g;
    __half* Ohb = g_Oh + base + (size_t)orow * DM;
    #pragma unroll
    for (int jn = 0; jn < 8; jn++) {
        int cc = jn * 8 + c2;
        *(uint32_t*)(Ohb + cc) =
            packh2(oacc[jn][0] * inv0, oacc[jn][1] * inv0);
        *(uint32_t*)(Ohb + 8 * DM + cc) =
            packh2(oacc[jn][2] * inv1, oacc[jn][3] * inv1);
    }
}

// ---------------------------------------------------------------------------
extern "C" void kernel_launch(void* const* d_in, const int* in_sizes, int n_in,
                              void* d_out, int out_size)
{
    (void)in_sizes; (void)n_in; (void)out_size;
    const float* q    = (const float*)d_in[0];
    const float* k    = (const float*)d_in[1];
    const float* v    = (const float*)d_in[2];
    const float* mask = (const float*)d_in[3];
    const float* wq_w = (const float*)d_in[4];
    const float* wq_b = (const float*)d_in[5];
    const float* wk_w = (const float*)d_in[6];
    const float* wk_b = (const float*)d_in[7];
    const float* wv_w = (const float*)d_in[8];
    const float* wv_b = (const float*)d_in[9];
    const float* pl_w = (const float*)d_in[10];
    const float* pl_b = (const float*)d_in[11];
    float* out = (float*)d_out;

    __half *Qh, *Kh, *Vh, *Oh, *xhi, *whi;
    cudaGetSymbolAddress((void**)&Qh, g_Qh);
    cudaGetSymbolAddress((void**)&Kh, g_Kh);
    cudaGetSymbolAddress((void**)&Vh, g_Vh);
    cudaGetSymbolAddress((void**)&Oh, g_Oh);
    cudaGetSymbolAddress((void**)&xhi, g_xhi);
    cudaGetSymbolAddress((void**)&whi, g_whi);

    cudaFuncSetAttribute(gemm_hmma, cudaFuncAttributeMaxDynamicSharedMemorySize,
                         GEMM_SMEM);
    cudaFuncSetAttribute(attn_mma, cudaFuncAttributeMaxDynamicSharedMemorySize,
                         ATTN_SMEM);

    const int NX = MROWS * DM;
    const int NW = DM * DM;
    dim3 gg(DM / BN, MROWS / BM);   // (8, 32)

    // Q projection (1/sqrt(64) folded in)
    conv_f16<<<NX / 2048, 256>>>(q, xhi, NX);
    conv_f16<<<NW / 2048, 256>>>(wq_w, whi, NW);
    gemm_hmma<<<gg, 256, GEMM_SMEM>>>(xhi, whi, wq_b, nullptr, Qh, 0.125f);
    // K projection
    conv_f16<<<NX / 2048, 256>>>(k, xhi, NX);
    conv_f16<<<NW / 2048, 256>>>(wk_w, whi, NW);
    gemm_hmma<<<gg, 256, GEMM_SMEM>>>(xhi, whi, wk_b, nullptr, Kh, 1.0f);
    // V projection
    conv_f16<<<NX / 2048, 256>>>(v, xhi, NX);
    conv_f16<<<NW / 2048, 256>>>(wv_w, whi, NW);
    gemm_hmma<<<gg, 256, GEMM_SMEM>>>(xhi, whi, wv_b, nullptr, Vh, 1.0f);

    // attention
    attn_mma<<<dim3(SEQ / 128, BATCH * NHEAD), 256, ATTN_SMEM>>>(mask);

    // output projection (fp32 out)
    conv_f16<<<NW / 2048, 256>>>(pl_w, whi, NW);
    gemm_hmma<<<gg, 256, GEMM_SMEM>>>(Oh, whi, pl_b, out, nullptr, 1.0f);
}

// round 14
// speedup vs baseline: 5.7131x; 1.0881x over previous
#include <cuda_runtime.h>
#include <cuda_fp16.h>
#include <cstdint>

#define BATCH  4
#define SEQ    1024
#define DM     1024
#define NHEAD  16
#define DEPTH  64
#define MROWS  (BATCH * SEQ)
#define NX (MROWS * DM)
#define NW (DM * DM)

// ---------------- scratch (device globals; allocation-free rule) ------------
__device__ __half g_Qh[(size_t)MROWS * DM];
__device__ __half g_Kh[(size_t)MROWS * DM];
__device__ __half g_Vh[(size_t)MROWS * DM];
__device__ __half g_Oh[(size_t)MROWS * DM];
__device__ __half g_xq[(size_t)NX];
__device__ __half g_xk[(size_t)NX];
__device__ __half g_xv[(size_t)NX];
__device__ __half g_wq[(size_t)NW];
__device__ __half g_wk[(size_t)NW];
__device__ __half g_wv[(size_t)NW];
__device__ __half g_wp[(size_t)NW];

// ---------------- helpers ----------------------------------------------------
__device__ __forceinline__ uint32_t smem_u32(const void* p) {
    uint32_t a;
    asm("{ .reg .u64 t; cvta.to.shared.u64 t, %1; cvt.u32.u64 %0, t; }"
        : "=r"(a) : "l"(p));
    return a;
}
__device__ __forceinline__ void ldm_x4(uint32_t* r, uint32_t addr) {
    asm volatile("ldmatrix.sync.aligned.m8n8.x4.shared.b16 {%0,%1,%2,%3}, [%4];"
                 : "=r"(r[0]), "=r"(r[1]), "=r"(r[2]), "=r"(r[3]) : "r"(addr));
}
__device__ __forceinline__ void ldm_x4_t(uint32_t* r, uint32_t addr) {
    asm volatile("ldmatrix.sync.aligned.m8n8.x4.trans.shared.b16 {%0,%1,%2,%3}, [%4];"
                 : "=r"(r[0]), "=r"(r[1]), "=r"(r[2]), "=r"(r[3]) : "r"(addr));
}
__device__ __forceinline__ void mma16816(float* d, const uint32_t* a,
                                         const uint32_t* b) {
    asm("mma.sync.aligned.m16n8k16.row.col.f32.f16.f16.f32 "
        "{%0,%1,%2,%3}, {%4,%5,%6,%7}, {%8,%9}, {%0,%1,%2,%3};"
        : "+f"(d[0]), "+f"(d[1]), "+f"(d[2]), "+f"(d[3])
        : "r"(a[0]), "r"(a[1]), "r"(a[2]), "r"(a[3]), "r"(b[0]), "r"(b[1]));
}
__device__ __forceinline__ uint32_t packh2(float a, float b) {
    __half2 h = __floats2half2_rn(a, b);
    return *(uint32_t*)&h;
}
#define CP_ASYNC16(saddr, gptr) \
    asm volatile("cp.async.cg.shared.global [%0], [%1], 16;" \
                 :: "r"(saddr), "l"(gptr))
#define CP_COMMIT() asm volatile("cp.async.commit_group;")
#define CP_WAIT1()  asm volatile("cp.async.wait_group 1;")
#define CP_WAIT0()  asm volatile("cp.async.wait_group 0;")

// ---------------- single mega-conv: all 7 fp32->fp16 tensors -----------------
__global__ __launch_bounds__(256)
void conv_all(const float* __restrict__ q, const float* __restrict__ k,
              const float* __restrict__ v, const float* __restrict__ wq,
              const float* __restrict__ wk, const float* __restrict__ wv,
              const float* __restrict__ wp,
              __half* __restrict__ xq, __half* __restrict__ xk,
              __half* __restrict__ xv, __half* __restrict__ dwq,
              __half* __restrict__ dwk, __half* __restrict__ dwv,
              __half* __restrict__ dwp)
{
    const float* src; __half* dst; int n;
    switch (blockIdx.y) {
        case 0:  src = q;  dst = xq;  n = NX; break;
        case 1:  src = k;  dst = xk;  n = NX; break;
        case 2:  src = v;  dst = xv;  n = NX; break;
        case 3:  src = wq; dst = dwq; n = NW; break;
        case 4:  src = wk; dst = dwk; n = NW; break;
        case 5:  src = wv; dst = dwv; n = NW; break;
        default: src = wp; dst = dwp; n = NW; break;
    }
    int i = (blockIdx.x * 256 + threadIdx.x) * 8;
    if (i >= n) return;
    float4 v0 = *(const float4*)(src + i);
    float4 v1 = *(const float4*)(src + i + 4);
    __half h[8] = {__float2half_rn(v0.x), __float2half_rn(v0.y),
                   __float2half_rn(v0.z), __float2half_rn(v0.w),
                   __float2half_rn(v1.x), __float2half_rn(v1.y),
                   __float2half_rn(v1.z), __float2half_rn(v1.w)};
    *(uint4*)(dst + i) = *(uint4*)h;
}

// ---------------- 1-pass HMMA GEMM, 3-stage cp.async pipeline ---------------
#define BM 128
#define BN 128
#define BKG 32
#define SKPG 40
#define GT_H (128 * SKPG)            // 5120 halves per tile
#define GSTAGE_H (2 * GT_H)          // A, W
#define GEMM_SMEM (3 * GSTAGE_H * 2) // 61440 bytes

__device__ __forceinline__ void gemm_issue(uint32_t sb, int buf, int k0,
    const __half* A0, const __half* W0, int t)
{
    const __half* bases[2] = {A0, W0};
    const uint32_t stb = sb + buf * (GSTAGE_H * 2);
    #pragma unroll
    for (int j = 0; j < 4; j++) {
        const int tile = j >> 1;
        const int r = t + (j & 1) * 256;   // 0..511
        const int row = r >> 2, c16 = r & 3;
        const __half* gp = bases[tile] + (size_t)row * DM + k0 + c16 * 8;
        uint32_t sa = stb + (tile * GT_H + row * SKPG + c16 * 8) * 2;
        CP_ASYNC16(sa, gp);
    }
    CP_COMMIT();
}

__global__ void __launch_bounds__(256, 2)
gemm_hmma(const __half* __restrict__ Ahi, const __half* __restrict__ Whi,
          const float* __restrict__ bias,
          float* __restrict__ Cf, __half* __restrict__ Chi, float scale)
{
    extern __shared__ __half sh[];
    const uint32_t sb = smem_u32(sh);

    const int t      = threadIdx.x;
    const int lane   = t & 31;
    const int wid    = t >> 5;
    const int warp_m = wid & 3;
    const int warp_n = wid >> 2;
    const int sub    = lane >> 3;
    const int l7     = lane & 7;
    const int bm     = blockIdx.y * BM;
    const int bn     = blockIdx.x * BN;

    const __half* A0 = Ahi + (size_t)bm * DM;
    const __half* W0 = Whi + (size_t)bn * DM;

    float acc[2][8][4];
    #pragma unroll
    for (int i = 0; i < 2; i++)
        #pragma unroll
        for (int j = 0; j < 8; j++)
            #pragma unroll
            for (int c = 0; c < 4; c++) acc[i][j][c] = 0.f;

    const uint32_t a_off =
        ((warp_m * 32 + (l7 | ((sub & 1) << 3))) * SKPG + ((sub >> 1) << 3)) * 2;
    const uint32_t b_off =
        ((warp_n * 64 + (l7 + ((sub >> 1) << 3))) * SKPG + ((sub & 1) << 3)) * 2;

    gemm_issue(sb, 0, 0, A0, W0, t);
    gemm_issue(sb, 1, BKG, A0, W0, t);

    const int NS = DM / BKG;   // 32
    for (int kc = 0; kc < NS; kc++) {
        if (kc + 1 < NS) CP_WAIT1(); else CP_WAIT0();
        __syncthreads();
        if (kc + 2 < NS)
            gemm_issue(sb, (kc + 2) % 3, (kc + 2) * BKG, A0, W0, t);

        const uint32_t bA = sb + (kc % 3) * (GSTAGE_H * 2);
        const uint32_t bW = bA + GT_H * 2;

        #pragma unroll
        for (int k16 = 0; k16 < 2; k16++) {
            const uint32_t ko = k16 * 32;
            uint32_t ah[2][4];
            #pragma unroll
            for (int im = 0; im < 2; im++)
                ldm_x4(ah[im], bA + a_off + im * (16 * SKPG * 2) + ko);
            #pragma unroll
            for (int jn16 = 0; jn16 < 4; jn16++) {
                uint32_t rh[4];
                ldm_x4(rh, bW + b_off + jn16 * (16 * SKPG * 2) + ko);
                mma16816(acc[0][jn16 * 2],     ah[0], rh);
                mma16816(acc[1][jn16 * 2],     ah[1], rh);
                mma16816(acc[0][jn16 * 2 + 1], ah[0], rh + 2);
                mma16816(acc[1][jn16 * 2 + 1], ah[1], rh + 2);
            }
        }
    }

    const int g  = lane >> 2;
    const int tc = (lane & 3) * 2;
    #pragma unroll
    for (int im = 0; im < 2; im++) {
        const int r0 = bm + warp_m * 32 + im * 16 + g;
        #pragma unroll
        for (int jn = 0; jn < 8; jn++) {
            const int c = bn + warp_n * 64 + jn * 8 + tc;
            const float b0 = bias[c], b1 = bias[c + 1];
            float v0 = (acc[im][jn][0] + b0) * scale;
            float v1 = (acc[im][jn][1] + b1) * scale;
            float v2 = (acc[im][jn][2] + b0) * scale;
            float v3 = (acc[im][jn][3] + b1) * scale;
            if (Cf) {
                *(float2*)(Cf + (size_t)r0 * DM + c) = make_float2(v0, v1);
                *(float2*)(Cf + (size_t)(r0 + 8) * DM + c) = make_float2(v2, v3);
            } else {
                *(uint32_t*)(Chi + (size_t)r0 * DM + c) = packh2(v0, v1);
                *(uint32_t*)(Chi + (size_t)(r0 + 8) * DM + c) = packh2(v2, v3);
            }
        }
    }
}

// ---------------- HMMA flash attention, 1-pass fp16, 3-stage pipeline -------
#define ATK  64
#define ASKP 72
#define AT_H (64 * ASKP)
#define ASTAGE_H (2 * AT_H)
#define ATTN_SMEM (3 * ASTAGE_H * 2)   // 55296 bytes

__device__ __forceinline__ void attn_issue(uint32_t sb, int buf, int k0,
    const __half* Khb, const __half* Vhb, int t)
{
    const uint32_t stb = sb + buf * (ASTAGE_H * 2);
    #pragma unroll
    for (int j = 0; j < 4; j++) {
        const int tile = j >> 1;           // 0=Kh, 1=Vh
        const int r = t + (j & 1) * 256;
        const int row = r >> 3, c16 = r & 7;
        const __half* gp = (tile ? Vhb : Khb) + (size_t)(k0 + row) * DM
                           + c16 * 8;
        uint32_t sa = stb + (tile * AT_H + row * ASKP + c16 * 8) * 2;
        CP_ASYNC16(sa, gp);
    }
    CP_COMMIT();
}

__global__ void __launch_bounds__(256, 2)
attn_mma(const float* __restrict__ mask)
{
    extern __shared__ __half sh[];
    const uint32_t sb = smem_u32(sh);

    const int t    = threadIdx.x;
    const int lane = t & 31;
    const int wid  = t >> 5;
    const int sub  = lane >> 3;
    const int l7   = lane & 7;
    const int g    = lane >> 2;
    const int c2   = (lane & 3) * 2;

    const int q0 = blockIdx.x * 128;
    const int bh = blockIdx.y;
    const int b  = bh >> 4;
    const int h  = bh & 15;

    const size_t base = (size_t)b * SEQ * DM + h * DEPTH;
    const __half* Qhb = g_Qh + base;
    const __half* Khb = g_Kh + base;
    const __half* Vhb = g_Vh + base;

    // ---- stage Q tile (128 rows x 64) into stage-0 area, read to regs ----
    #pragma unroll
    for (int j = 0; j < 4; j++) {
        const int r = t + j * 256;            // 0..1023
        const int row = r >> 3, c16 = r & 7;
        const __half* src = Qhb + (size_t)(q0 + row) * DM + c16 * 8;
        __half* dst = sh + (row >> 6) * AT_H + (row & 63) * ASKP + c16 * 8;
        *(uint4*)dst = *(const uint4*)src;
    }
    __syncthreads();

    uint32_t qh[4][4];
    {
        const int qrow = wid * 16 + (l7 | ((sub & 1) << 3));
        const uint32_t hb = sb + ((qrow >> 6) * AT_H + (qrow & 63) * ASKP) * 2;
        #pragma unroll
        for (int kk = 0; kk < 4; kk++)
            ldm_x4(qh[kk], hb + (((sub >> 1) << 3) + kk * 16) * 2);
    }
    __syncthreads();   // Q in regs before chunk-0 prefetch overwrites stage 0

    float oacc[8][4];
    #pragma unroll
    for (int j = 0; j < 8; j++)
        #pragma unroll
        for (int c = 0; c < 4; c++) oacc[j][c] = 0.f;
    float rmax[2] = {-1e30f, -1e30f};
    float rsum[2] = {0.f, 0.f};

    const int mrow = q0 + wid * 16 + g;

    attn_issue(sb, 0, 0, Khb, Vhb, t);
    attn_issue(sb, 1, ATK, Khb, Vhb, t);

    const int NC = SEQ / ATK;   // 16
    for (int kc = 0; kc < NC; kc++) {
        const int k0 = kc * ATK;
        if (kc + 1 < NC) CP_WAIT1(); else CP_WAIT0();
        __syncthreads();
        if (kc + 2 < NC)
            attn_issue(sb, (kc + 2) % 3, (kc + 2) * ATK, Khb, Vhb, t);

        const uint32_t stb  = sb + (kc % 3) * (ASTAGE_H * 2);
        const uint32_t bKh2 = stb;
        const uint32_t bVh2 = stb + AT_H * 2;

        // ---- S = Qh K^T ----
        float sacc[8][4];
        #pragma unroll
        for (int j = 0; j < 8; j++)
            #pragma unroll
            for (int c = 0; c < 4; c++) sacc[j][c] = 0.f;

        #pragma unroll
        for (int kk = 0; kk < 4; kk++) {
            #pragma unroll
            for (int jp = 0; jp < 4; jp++) {
                uint32_t rh[4];
                uint32_t off = ((jp * 16 + l7 + ((sub >> 1) << 3)) * ASKP
                                + ((sub & 1) << 3) + kk * 16) * 2;
                ldm_x4(rh, bKh2 + off);
                mma16816(sacc[2 * jp],     qh[kk], rh);
                mma16816(sacc[2 * jp + 1], qh[kk], rh + 2);
            }
        }

        // ---- mask ----
        #pragma unroll
        for (int j = 0; j < 8; j++) {
            int col = k0 + j * 8 + c2;
            float2 m0 = *(const float2*)(mask + (size_t)mrow * SEQ + col);
            float2 m1 = *(const float2*)(mask + (size_t)(mrow + 8) * SEQ + col);
            sacc[j][0] -= 1e9f * m0.x; sacc[j][1] -= 1e9f * m0.y;
            sacc[j][2] -= 1e9f * m1.x; sacc[j][3] -= 1e9f * m1.y;
        }

        // ---- online softmax ----
        #pragma unroll
        for (int r = 0; r < 2; r++) {
            float mx = -1e30f;
            #pragma unroll
            for (int j = 0; j < 8; j++)
                mx = fmaxf(mx, fmaxf(sacc[j][2 * r], sacc[j][2 * r + 1]));
            mx = fmaxf(mx, __shfl_xor_sync(0xffffffffu, mx, 1));
            mx = fmaxf(mx, __shfl_xor_sync(0xffffffffu, mx, 2));
            float nm   = fmaxf(rmax[r], mx);
            float corr = __expf(rmax[r] - nm);
            rmax[r] = nm;
            float ps = 0.f;
            #pragma unroll
            for (int j = 0; j < 8; j++) {
                float p0 = __expf(sacc[j][2 * r] - nm);
                float p1 = __expf(sacc[j][2 * r + 1] - nm);
                sacc[j][2 * r] = p0; sacc[j][2 * r + 1] = p1;
                ps += p0 + p1;
            }
            ps += __shfl_xor_sync(0xffffffffu, ps, 1);
            ps += __shfl_xor_sync(0xffffffffu, ps, 2);
            rsum[r] = rsum[r] * corr + ps;
            #pragma unroll
            for (int jn = 0; jn < 8; jn++) {
                oacc[jn][2 * r]     *= corr;
                oacc[jn][2 * r + 1] *= corr;
            }
        }

        // ---- O += P @ Vh ----
        #pragma unroll
        for (int kk = 0; kk < 4; kk++) {
            uint32_t ph[4];
            ph[0] = packh2(sacc[2 * kk][0],     sacc[2 * kk][1]);
            ph[1] = packh2(sacc[2 * kk][2],     sacc[2 * kk][3]);
            ph[2] = packh2(sacc[2 * kk + 1][0], sacc[2 * kk + 1][1]);
            ph[3] = packh2(sacc[2 * kk + 1][2], sacc[2 * kk + 1][3]);
            #pragma unroll
            for (int jd = 0; jd < 4; jd++) {
                uint32_t vh4[4];
                uint32_t off = ((kk * 16 + ((sub & 1) << 3) + l7) * ASKP
                                + jd * 16 + ((sub >> 1) << 3)) * 2;
                ldm_x4_t(vh4, bVh2 + off);
                mma16816(oacc[2 * jd],     ph, vh4);
                mma16816(oacc[2 * jd + 1], ph, vh4 + 2);
            }
        }
    }

    // ---- epilogue: normalize, write fp16 ----
    const float inv0 = 1.0f / rsum[0];
    const float inv1 = 1.0f / rsum[1];
    const int orow = q0 + wid * 16 + g;
    __half* Ohb = g_Oh + base + (size_t)orow * DM;
    #pragma unroll
    for (int jn = 0; jn < 8; jn++) {
        int cc = jn * 8 + c2;
        *(uint32_t*)(Ohb + cc) =
            packh2(oacc[jn][0] * inv0, oacc[jn][1] * inv0);
        *(uint32_t*)(Ohb + 8 * DM + cc) =
            packh2(oacc[jn][2] * inv1, oacc[jn][3] * inv1);
    }
}

// ---------------------------------------------------------------------------
extern "C" void kernel_launch(void* const* d_in, const int* in_sizes, int n_in,
                              void* d_out, int out_size)
{
    (void)in_sizes; (void)n_in; (void)out_size;
    const float* q    = (const float*)d_in[0];
    const float* k    = (const float*)d_in[1];
    const float* v    = (const float*)d_in[2];
    const float* mask = (const float*)d_in[3];
    const float* wq_w = (const float*)d_in[4];
    const float* wq_b = (const float*)d_in[5];
    const float* wk_w = (const float*)d_in[6];
    const float* wk_b = (const float*)d_in[7];
    const float* wv_w = (const float*)d_in[8];
    const float* wv_b = (const float*)d_in[9];
    const float* pl_w = (const float*)d_in[10];
    const float* pl_b = (const float*)d_in[11];
    float* out = (float*)d_out;

    __half *Qh, *Kh, *Vh, *Oh, *xq, *xk, *xv, *wq, *wk, *wv, *wp;
    cudaGetSymbolAddress((void**)&Qh, g_Qh);
    cudaGetSymbolAddress((void**)&Kh, g_Kh);
    cudaGetSymbolAddress((void**)&Vh, g_Vh);
    cudaGetSymbolAddress((void**)&Oh, g_Oh);
    cudaGetSymbolAddress((void**)&xq, g_xq);
    cudaGetSymbolAddress((void**)&xk, g_xk);
    cudaGetSymbolAddress((void**)&xv, g_xv);
    cudaGetSymbolAddress((void**)&wq, g_wq);
    cudaGetSymbolAddress((void**)&wk, g_wk);
    cudaGetSymbolAddress((void**)&wv, g_wv);
    cudaGetSymbolAddress((void**)&wp, g_wp);

    cudaFuncSetAttribute(gemm_hmma, cudaFuncAttributeMaxDynamicSharedMemorySize,
                         GEMM_SMEM);
    cudaFuncSetAttribute(attn_mma, cudaFuncAttributeMaxDynamicSharedMemorySize,
                         ATTN_SMEM);

    dim3 gg(DM / BN, MROWS / BM);   // (8, 32)

    // all 7 conversions in one launch (depend only on inputs)
    conv_all<<<dim3(NX / 2048, 7), 256>>>(q, k, v, wq_w, wk_w, wv_w, pl_w,
                                          xq, xk, xv, wq, wk, wv, wp);

    // projections (1/sqrt(64) folded into Q)
    gemm_hmma<<<gg, 256, GEMM_SMEM>>>(xq, wq, wq_b, nullptr, Qh, 0.125f);
    gemm_hmma<<<gg, 256, GEMM_SMEM>>>(xk, wk, wk_b, nullptr, Kh, 1.0f);
    gemm_hmma<<<gg, 256, GEMM_SMEM>>>(xv, wv, wv_b, nullptr, Vh, 1.0f);

    // attention
    attn_mma<<<dim3(SEQ / 128, BATCH * NHEAD), 256, ATTN_SMEM>>>(mask);

    // output projection (fp32 out)
    gemm_hmma<<<gg, 256, GEMM_SMEM>>>(Oh, wp, pl_b, out, nullptr, 1.0f);
}